// round 11
// baseline (speedup 1.0000x reference)
#include <cuda_runtime.h>
#include <cuda_fp16.h>
#include <math.h>
#include <stdint.h>

#define BQ  128
#define KK_ 49
#define DD  512
#define EE  256
#define VV  10000
#define TT  20
#define G4  2048
#define NW  2176          // padded gates+Wg width: 2048 + 49 -> 17*128
typedef __half fp16;

// -------------------- device scratch (static) --------------------
__device__ __align__(128) fp16 g_embf[BQ*TT*EE];
__device__ __align__(128) fp16 g_glf[BQ*DD];
__device__ __align__(128) fp16 g_wihef[G4*EE];
__device__ __align__(128) fp16 g_wcatf[3072*DD];   // [Winit_h;Winit_m;W_ih_D]
__device__ __align__(128) fp16 g_wc2f[NW*DD];      // [W_hh;Wg;0pad]
__device__ __align__(128) fp16 g_wvf[KK_*DD];
__device__ __align__(128) fp16 g_wpf[VV*DD];
__device__ __align__(128) fp16 g_spf[BQ*KK_*DD];
__device__ __align__(128) fp16 g_hf[BQ*DD];
__device__ __align__(128) fp16 g_sf[BQ*TT*DD];     // compacted active rows
__device__ __align__(128) float g_gatesx[BQ*TT*G4];// compacted active rows
__device__ __align__(128) float g_vproj[BQ*KK_*KK_];
__device__ __align__(128) float g_part[BQ*8*NW];
__device__ __align__(128) float g_ipart[4][BQ*3072];
__device__ __align__(128) float g_vpart[2][BQ*KK_*KK_];
__device__ int g_rmap[BQ*TT];     // compact row -> b*TT+t
__device__ int g_mact;            // number of active rows
__device__ unsigned g_bgrp[17];   // 2-level barrier group counters (monotonic)
__device__ unsigned g_brt;        // root counter (monotonic)
__device__ unsigned g_bgen;       // generation (monotonic)

// -------------------- helpers --------------------
__device__ __forceinline__ uint32_t su(const void* p) {
    return (uint32_t)__cvta_generic_to_shared(p);
}
__device__ __forceinline__ void cpa16(uint32_t sa, const void* ga, uint32_t sz) {
    asm volatile("cp.async.cg.shared.global [%0],[%1],16,%2;\n" :: "r"(sa), "l"(ga), "r"(sz));
}
__device__ __forceinline__ void cpcommit() { asm volatile("cp.async.commit_group;\n"); }
template<int N> __device__ __forceinline__ void cpwait() {
    asm volatile("cp.async.wait_group %0;\n" :: "n"(N));
}
__device__ __forceinline__ void ldsm4(uint32_t* r, uint32_t a) {
    asm volatile("ldmatrix.sync.aligned.m8n8.x4.shared.b16 {%0,%1,%2,%3},[%4];\n"
                 : "=r"(r[0]), "=r"(r[1]), "=r"(r[2]), "=r"(r[3]) : "r"(a));
}
__device__ __forceinline__ void mmah(float* c, const uint32_t* a, uint32_t b0, uint32_t b1) {
    asm volatile(
        "mma.sync.aligned.m16n8k16.row.col.f32.f16.f16.f32 "
        "{%0,%1,%2,%3},{%4,%5,%6,%7},{%8,%9},{%0,%1,%2,%3};\n"
        : "+f"(c[0]), "+f"(c[1]), "+f"(c[2]), "+f"(c[3])
        : "r"(a[0]), "r"(a[1]), "r"(a[2]), "r"(a[3]), "r"(b0), "r"(b1));
}
__device__ __forceinline__ float fsig(float x) { return 1.f / (1.f + __expf(-x)); }
__device__ __forceinline__ float ftanh(float x) {
    float e = __expf(2.f * x);
    return 1.f - 2.f / (e + 1.f);
}

// -------------------- fp32 -> fp16 segmented converter --------------------
struct Seg { const float4* src; uint2* dst; int srcld4; int lc4; long long start; };
struct SegArr { Seg s[10]; long long total; };

__global__ void conv_all(SegArr sa) {
    long long i = (long long)blockIdx.x * blockDim.x + threadIdx.x;
    if (i >= sa.total) return;
    int k = 0;
#pragma unroll
    for (int j = 1; j < 10; j++) if (i >= sa.s[j].start) k = j;
    Seg sg = sa.s[k];
    long long idx = i - sg.start;
    int row = (int)(idx >> sg.lc4);
    int c   = (int)(idx & ((1 << sg.lc4) - 1));
    float4 v = sg.src[(long long)row * sg.srcld4 + c];
    __half2 a = __floats2half2_rn(v.x, v.y);
    __half2 b = __floats2half2_rn(v.z, v.w);
    uint2 o;
    o.x = *reinterpret_cast<uint32_t*>(&a);
    o.y = *reinterpret_cast<uint32_t*>(&b);
    sg.dst[idx] = o;
}

// -------------------- active-row map --------------------
__global__ void build_map(const int* __restrict__ lengths) {
    __shared__ int cnt[20], off[21];
    int tid = threadIdx.x;
    if (tid < 20) {
        int c = 0;
        for (int b = 0; b < BQ; b++) c += (lengths[b] > tid);
        cnt[tid] = c;
    }
    __syncthreads();
    if (tid == 0) {
        off[0] = 0;
        for (int t = 0; t < 20; t++) off[t + 1] = off[t] + cnt[t];
        g_mact = off[20];
    }
    __syncthreads();
    for (int t = 0; t < 20; t++)
        for (int b = tid; b < cnt[t]; b += 256)
            g_rmap[off[t] + b] = b * TT + t;
}

// -------------------- zero-fill inactive output rows --------------------
__global__ void zfill(const int* __restrict__ lengths, float* __restrict__ out) {
    int row = blockIdx.x;
    int b = row / TT, t = row % TT;
    if (lengths[b] > t) return;
    float4 z = make_float4(0.f, 0.f, 0.f, 0.f);
    float4* o = reinterpret_cast<float4*>(out + (size_t)row * VV);
    for (int i = threadIdx.x; i < VV / 4; i += 256) o[i] = z;
}

// -------------------- embedding gather (compact, fp16) --------------------
__global__ void gather_emb(const int* __restrict__ cap, const float* __restrict__ emb) {
    int i = blockIdx.x * blockDim.x + threadIdx.x;
    if (i >= BQ * TT * (EE / 4)) return;
    int r = i >> 6, e4 = i & 63;
    if (r >= g_mact) return;
    int tok = cap[g_rmap[r]];
    float4 v = reinterpret_cast<const float4*>(emb)[(size_t)tok * 64 + e4];
    __half2 a = __floats2half2_rn(v.x, v.y);
    __half2 b = __floats2half2_rn(v.z, v.w);
    uint2 o;
    o.x = *reinterpret_cast<uint32_t*>(&a);
    o.y = *reinterpret_cast<uint32_t*>(&b);
    reinterpret_cast<uint2*>(g_embf)[(size_t)r * 64 + e4] = o;
}

// -------------------- generalized fp16 GEMM (128x128, 2-stage pipeline) --------------
// C[M,N] = A[M,K]@B[N,K]^T (+bias, optional split-K z, optional compact row map)
#define SST   40
#define FMATB (128 * SST)

__global__ void __launch_bounds__(256, 2) gemm_f16(
    const fp16* __restrict__ A, int lda,
    const fp16* __restrict__ B, int ldb,
    float* __restrict__ C, int ldc, int M, int N, int K,   // K = per-z slice
    const float* __restrict__ bias,
    float* __restrict__ Cpart, long partStride,
    const int* __restrict__ useMact,     // if set: M = g_mact (device), early-exit
    int useRmap)                         // if set: epilogue row = g_rmap[gm]
{
    int Meff = M;
    if (useMact) { Meff = g_mact; if (blockIdx.y * 128 >= Meff) return; }

    extern __shared__ __align__(16) char smraw[];
    fp16* sm = (fp16*)smraw;                     // [2][2][FMATB]

    const int tid = threadIdx.x;
    const int bm = blockIdx.y * 128, bn = blockIdx.x * 128;
    const int kz = blockIdx.z;
    float* Cw = Cpart ? (Cpart + (size_t)kz * partStride) : C;

    const int w = tid >> 5, lane = tid & 31;
    const int wm = w >> 2, wn = w & 3;
    const int g = lane >> 2, tg = lane & 3;
    const int lrow = lane & 15, lcol = (lane >> 4) * 8;
    const int ldrow = tid >> 1, ldch = (tid & 1) * 2;

    const fp16* aSrc = A + (size_t)kz * K + (size_t)(bm + ldrow) * lda + ldch * 8;
    int gn_l = bn + ldrow;
    uint32_t szb = (gn_l < N) ? 16u : 0u;
    if (gn_l >= N) gn_l = 0;
    const fp16* bSrc = B + (size_t)kz * K + (size_t)gn_l * ldb + ldch * 8;
    const uint32_t da = su(sm + ldrow * SST + ldch * 8);
    const uint32_t db = da + FMATB * 2;

    float acc[4][4][4];
#pragma unroll
    for (int i = 0; i < 4; i++)
#pragma unroll
        for (int j = 0; j < 4; j++)
#pragma unroll
            for (int q = 0; q < 4; q++) acc[i][j][q] = 0.f;

    auto issue = [&](int stg, int k0) {
        uint32_t so = (uint32_t)(stg * 2 * FMATB) * 2;
        cpa16(da + so,      aSrc + k0,     16);
        cpa16(da + so + 16, aSrc + k0 + 8, 16);
        cpa16(db + so,      bSrc + k0,     szb);
        cpa16(db + so + 16, bSrc + k0 + 8, szb);
    };

    const int niter = K / 32;
    issue(0, 0);
    cpcommit();
    int st = 0;
    for (int it = 0; it < niter; ++it) {
        if (it + 1 < niter) {
            issue(st ^ 1, (it + 1) * 32);
            cpcommit();
            cpwait<1>();
        } else {
            cpwait<0>();
        }
        __syncthreads();
        const fp16* base = sm + st * 2 * FMATB;
#pragma unroll
        for (int ks = 0; ks < 32; ks += 16) {
            uint32_t ah[4][4], bh[2][4];
#pragma unroll
            for (int mi = 0; mi < 4; mi++)
                ldsm4(ah[mi], su(base + (wm * 64 + mi * 16 + lrow) * SST + ks + lcol));
#pragma unroll
            for (int p = 0; p < 2; p++)
                ldsm4(bh[p], su(base + FMATB + (wn * 32 + p * 16 + lrow) * SST + ks + lcol));
#pragma unroll
            for (int mi = 0; mi < 4; mi++)
#pragma unroll
                for (int ni = 0; ni < 4; ni++) {
                    const int p = ni >> 1, q = ni & 1;
                    mmah(acc[mi][ni], ah[mi], bh[p][q], bh[p][q + 2]);
                }
        }
        __syncthreads();
        st ^= 1;
    }

#pragma unroll
    for (int mi = 0; mi < 4; mi++)
#pragma unroll
        for (int ni = 0; ni < 4; ni++) {
            int gn0 = bn + wn * 32 + ni * 8 + tg * 2;
#pragma unroll
            for (int half = 0; half < 2; half++) {
                int gm = bm + wm * 64 + mi * 16 + g + half * 8;
                if (gm >= Meff) continue;
                int orow = useRmap ? g_rmap[gm] : gm;
#pragma unroll
                for (int q = 0; q < 2; q++) {
                    int gn = gn0 + q;
                    if (gn >= N) continue;
                    float v = acc[mi][ni][half * 2 + q];
                    if (bias) v += bias[gn];
                    Cw[(size_t)orow * ldc + gn] = v;
                }
            }
        }
}

// -------------------- 2-level grid barrier (monotonic, replay-safe) --------------------
__device__ __forceinline__ void gridbar2(int grp, unsigned rr) {
    __syncthreads();
    if (threadIdx.x == 0) {
        unsigned old;
        asm volatile("atom.add.release.gpu.u32 %0,[%1],1;"
                     : "=r"(old) : "l"(&g_bgrp[grp]) : "memory");
        if (old == rr * 8u + 7u) {
            unsigned old2;
            asm volatile("atom.add.release.gpu.u32 %0,[%1],1;"
                         : "=r"(old2) : "l"(&g_brt) : "memory");
            if (old2 == rr * 17u + 16u) {
                asm volatile("st.release.gpu.u32 [%0],%1;"
                             :: "l"(&g_bgen), "r"(rr + 1u) : "memory");
            }
        }
        unsigned v;
        do {
            asm volatile("ld.acquire.gpu.u32 %0,[%1];"
                         : "=r"(v) : "l"(&g_bgen) : "memory");
        } while ((int)(v - (rr + 1u)) < 0);
    }
    __syncthreads();
}

// -------------------- persistent recurrence kernel (fp16 MMA, length-aware) --------
#define RST 72
#define RMATB (128 * RST)

__global__ __launch_bounds__(256, 1) void recur_kernel(
    const float* __restrict__ b_hh,
    const int*   __restrict__ lengths,
    const float* __restrict__ bg,
    const float* __restrict__ wh,
    const float* __restrict__ bh_att,
    const float* __restrict__ b_init_h,
    const float* __restrict__ b_init_m,
    const float* __restrict__ b_ih,
    const float* __restrict__ bv)
{
    extern __shared__ __align__(16) char dsm[];
    fp16* sA = (fp16*)dsm;             // [128][RST]
    fp16* sB = sA + RMATB;             // [128][RST]
    float* sh_gh    = (float*)(dsm + 2 * RMATB * 2);
    float* sh_z     = sh_gh + 52;
    float* sh_alpha = sh_z + 52;
    int*   rs_cnt   = (int*)(sh_alpha + 52);   // [21]
    int*   rs_off   = rs_cnt + 21;             // [22]

    const int c = blockIdx.x;
    const int tid = threadIdx.x;
    const int kc = c & 7, cg = c >> 3, kbase = kc * 64;   // cg in 0..16
    const int grp = cg;
    const int b = c;                                      // phase2 owner (b<128)
    const int w = tid >> 5, lane = tid & 31;
    const int wm = w >> 2, wn = w & 3;
    const int g = lane >> 2, tg = lane & 3;
    const int lrow = lane & 15, lcol = (lane >> 4) * 8;
    const int wid = w;
    const float bh0 = bh_att[0];

    unsigned rbase;
    asm volatile("ld.acquire.gpu.u32 %0,[%1];" : "=r"(rbase) : "l"(&g_bgen) : "memory");
    unsigned round = 0;

    float hp[2], mr[2], gb[8];
    int len = 0;

    // ---- prologue: cnt/off arrays + per-batch init reduce + W slice preload ----
    if (tid < 21) {
        int cc = 0;
        for (int bb = 0; bb < BQ; bb++) cc += (lengths[bb] > tid);
        rs_cnt[tid] = cc;
    }
    __syncthreads();
    if (tid == 0) {
        rs_off[0] = 0;
        for (int u = 0; u < 21; u++) rs_off[u + 1] = rs_off[u] + rs_cnt[u];
    }
    __syncthreads();

    if (b < BQ) {
        len = lengths[b];
#pragma unroll
        for (int j = 0; j < 12; j++) {
            int n = tid + j * 256;
            float v = g_ipart[0][b * 3072 + n] + g_ipart[1][b * 3072 + n]
                    + g_ipart[2][b * 3072 + n] + g_ipart[3][b * 3072 + n];
            if (j < 2) {
                v += b_init_h[n];
                hp[j] = v;
                g_hf[b * DD + n] = __float2half(v);
            } else if (j < 4) {
                mr[j - 2] = v + b_init_m[n - 512];
            } else {
                int col = n - 1024;
                gb[j - 4] = v + b_ih[col] + b_hh[col];
            }
        }
        for (int i = tid; i < KK_ * KK_; i += 256) {
            int r = b * KK_ + i / KK_, q = i % KK_;
            g_vproj[(size_t)r * KK_ + q] =
                g_vpart[0][(size_t)r * KK_ + q] + g_vpart[1][(size_t)r * KK_ + q] + bv[q];
        }
    }
#pragma unroll
    for (int j = 0; j < 4; j++) {
        int cid = tid + j * 256;
        int row = cid >> 3, ch = cid & 7;
        *(float4*)(sB + row * RST + ch * 8) =
            *(const float4*)(g_wc2f + (size_t)(cg * 128 + row) * DD + kbase + ch * 8);
    }
    gridbar2(grp, rbase + round); round++;

    for (int t = 0; t <= TT; t++) {
        const int need = (t == 0) ? BQ : rs_cnt[t - 1];   // batch rows needed this iter
        // ---------------- GEMM: [gates(t); gh(t-1)] = h(t-1) @ W_cat^T ----------------
        {
#pragma unroll
            for (int j = 0; j < 4; j++) {
                int cid = tid + j * 256;
                int row = cid >> 3, ch = cid & 7;
                *(float4*)(sA + row * RST + ch * 8) =
                    *(const float4*)(g_hf + (size_t)row * DD + kbase + ch * 8);
            }
            __syncthreads();

            float acc[4][4][4];
#pragma unroll
            for (int i = 0; i < 4; i++)
#pragma unroll
                for (int j = 0; j < 4; j++)
#pragma unroll
                    for (int q = 0; q < 4; q++) acc[i][j][q] = 0.f;

            const int nmi_raw = (need - wm * 64 + 15) >> 4;
            const int nmi = nmi_raw < 0 ? 0 : (nmi_raw > 4 ? 4 : nmi_raw);

#pragma unroll
            for (int ks = 0; ks < 64; ks += 16) {
                uint32_t ah[4][4], bh2[2][4];
#pragma unroll
                for (int p = 0; p < 2; p++)
                    ldsm4(bh2[p], su(sB + (wn * 32 + p * 16 + lrow) * RST + ks + lcol));
#pragma unroll 4
                for (int mi = 0; mi < nmi; mi++) {
                    ldsm4(ah[mi], su(sA + (wm * 64 + mi * 16 + lrow) * RST + ks + lcol));
#pragma unroll
                    for (int ni = 0; ni < 4; ni++) {
                        const int p = ni >> 1, q = ni & 1;
                        mmah(acc[mi][ni], ah[mi], bh2[p][q], bh2[p][q + 2]);
                    }
                }
            }

#pragma unroll 4
            for (int mi = 0; mi < nmi; mi++)
#pragma unroll
                for (int ni = 0; ni < 4; ni++) {
                    int gn0 = wn * 32 + ni * 8 + tg * 2;
#pragma unroll
                    for (int half = 0; half < 2; half++) {
                        int gm = wm * 64 + mi * 16 + g + half * 8;   // batch row
                        if (gm >= need) continue;
                        float* pr = g_part + (size_t)gm * (8 * NW) + kc * NW + cg * 128 + gn0;
                        pr[0] = acc[mi][ni][half * 2 + 0];
                        pr[1] = acc[mi][ni][half * 2 + 1];
                    }
                }
        }
        gridbar2(grp, rbase + round); round++;
        // ---------------- phase 2 (CTA b < 128) ----------------
        if (b < BQ) {
            const float* pp = g_part + (size_t)b * (8 * NW);
            // ---- attention for step t-1 ----
            if (t >= 1 && len > t - 1) {
                if (tid < KK_) {
                    float s = bg[tid];
#pragma unroll
                    for (int q = 0; q < 8; q++) s += pp[q * NW + 2048 + tid];
                    sh_gh[tid] = s;
                }
                __syncthreads();
                for (int k = wid; k < KK_; k += 8) {
                    const float* vp = g_vproj + (size_t)(b * KK_ + k) * KK_;
                    float s = 0.f;
                    for (int q = lane; q < KK_; q += 32) s += ftanh(vp[q] + sh_gh[q]) * wh[q];
#pragma unroll
                    for (int o = 16; o; o >>= 1) s += __shfl_xor_sync(0xffffffffu, s, o);
                    if (lane == 0) sh_z[k] = s + bh0;
                }
                __syncthreads();
                if (wid == 0) {
                    float mx = -3.0e38f;
                    for (int k = lane; k < KK_; k += 32) mx = fmaxf(mx, sh_z[k]);
#pragma unroll
                    for (int o = 16; o; o >>= 1) mx = fmaxf(mx, __shfl_xor_sync(0xffffffffu, mx, o));
                    float sm = 0.f;
                    for (int k = lane; k < KK_; k += 32) { float e = __expf(sh_z[k] - mx); sh_alpha[k] = e; sm += e; }
#pragma unroll
                    for (int o = 16; o; o >>= 1) sm += __shfl_xor_sync(0xffffffffu, sm, o);
                    float inv = 1.f / sm;
                    for (int k = lane; k < KK_; k += 32) sh_alpha[k] *= inv;
                }
                __syncthreads();
                const fp16* sp = g_spf + (size_t)b * KK_ * DD;
                const int spos = rs_off[t - 1] + b;      // compact row for (b, t-1)
#pragma unroll
                for (int j = 0; j < 2; j++) {
                    int d = tid + j * 256;
                    float cc = 0.f;
#pragma unroll
                    for (int k = 0; k < KK_; k++)
                        cc = fmaf(sh_alpha[k], __half2float(sp[(size_t)k * DD + d]), cc);
                    float sv = cc + hp[j];
                    g_sf[(size_t)spos * DD + d] = __float2half(sv);
                }
            }
            // ---- LSTM for step t ----
            if (t < TT && len > t) {
                const float* gx = g_gatesx + (size_t)(rs_off[t] + b) * G4;   // compact
#pragma unroll
                for (int j = 0; j < 2; j++) {
                    int d = tid + j * 256;
                    float gi = gx[d]        + gb[j];
                    float gf = gx[512 + d]  + gb[2 + j];
                    float gg = gx[1024 + d] + gb[4 + j];
                    float go = gx[1536 + d] + gb[6 + j];
#pragma unroll
                    for (int q = 0; q < 8; q++) {
                        const float* p = pp + q * NW;
                        gi += p[d]; gf += p[512 + d]; gg += p[1024 + d]; go += p[1536 + d];
                    }
                    float ig = fsig(gi), fg = fsig(gf), og = fsig(go);
                    float gt = ftanh(gg);
                    float mn = fg * mr[j] + ig * gt;
                    float hv = og * ftanh(mn);
                    mr[j] = mn;
                    hp[j] = hv;
                    g_hf[(size_t)b * DD + d] = __float2half(hv);
                }
            }
        }
        gridbar2(grp, rbase + round); round++;
    }
}

// -------------------- launch --------------------
extern "C" void kernel_launch(void* const* d_in, const int* in_sizes, int n_in,
                              void* d_out, int out_size)
{
    const float* spatial      = (const float*)d_in[0];
    const float* global_feats = (const float*)d_in[1];
    const int*   captions     = (const int*)d_in[2];
    const int*   lengths      = (const int*)d_in[3];
    const float* emb          = (const float*)d_in[4];
    const float* W_init_h     = (const float*)d_in[5];
    const float* b_init_h     = (const float*)d_in[6];
    const float* W_init_m     = (const float*)d_in[7];
    const float* b_init_m     = (const float*)d_in[8];
    const float* W_ih         = (const float*)d_in[9];
    const float* b_ih         = (const float*)d_in[10];
    const float* W_hh         = (const float*)d_in[11];
    const float* b_hh         = (const float*)d_in[12];
    const float* Wv           = (const float*)d_in[13];
    const float* bv           = (const float*)d_in[14];
    const float* Wg           = (const float*)d_in[15];
    const float* bg           = (const float*)d_in[16];
    const float* wh           = (const float*)d_in[17];
    const float* bh_att       = (const float*)d_in[18];
    const float* Wp           = (const float*)d_in[19];
    const float* bp           = (const float*)d_in[20];
    float* out = (float*)d_out;

#define GETP(var, sym) void* var; cudaGetSymbolAddress(&var, sym)
    GETP(p_embf, g_embf);    GETP(p_glf, g_glf);
    GETP(p_wihef, g_wihef);  GETP(p_wcatf, g_wcatf);
    GETP(p_wc2f, g_wc2f);    GETP(p_wvf, g_wvf);
    GETP(p_wpf, g_wpf);      GETP(p_spf, g_spf);
    GETP(p_sf, g_sf);
    GETP(p_gatesx, g_gatesx);
    GETP(p_ipart, g_ipart);  GETP(p_vpart, g_vpart);
    GETP(p_mact, g_mact);
#undef GETP

    const int FSM = 2 * 2 * FMATB * 2;                       // 40960 B
    const int RSM = 2 * RMATB * 2 + (3 * 52) * 4 + 43 * 4 + 64;
    cudaFuncSetAttribute(gemm_f16, cudaFuncAttributeMaxDynamicSharedMemorySize, FSM);
    cudaFuncSetAttribute(recur_kernel, cudaFuncAttributeMaxDynamicSharedMemorySize, RSM);

    // ---- 0. active-row map ----
    build_map<<<1, 256>>>(lengths);

    // ---- 1. convert all fp32 operands to fp16 ----
    SegArr sa;
    long long pos = 0;
    auto seg = [&](int i, const float* src, void* dst, int srcld, int cols, int rows) {
        sa.s[i].src = (const float4*)src;
        sa.s[i].dst = (uint2*)dst;
        sa.s[i].srcld4 = srcld / 4;
        sa.s[i].lc4 = (cols / 4 == 64) ? 6 : 7;
        sa.s[i].start = pos;
        pos += (long long)rows * (cols / 4);
    };
    seg(0, global_feats, p_glf, DD, DD, BQ);
    seg(1, W_init_h, p_wcatf, DD, DD, DD);
    seg(2, W_init_m, (fp16*)p_wcatf + 512 * DD, DD, DD, DD);
    seg(3, W_ih, p_wihef, EE + DD, EE, G4);
    seg(4, W_ih + EE, (fp16*)p_wcatf + 1024 * DD, EE + DD, DD, G4);
    seg(5, W_hh, p_wc2f, DD, DD, G4);
    seg(6, Wg, (fp16*)p_wc2f + 2048 * DD, DD, DD, KK_);
    seg(7, Wv, p_wvf, DD, DD, KK_);
    seg(8, Wp, p_wpf, DD, DD, VV);
    seg(9, spatial, p_spf, DD, DD, BQ * KK_);
    sa.total = pos;
    conv_all<<<(unsigned)((pos + 255) / 256), 256>>>(sa);

    // ---- 2. gather caption embeddings (compact, fp16) ----
    gather_emb<<<(BQ * TT * (EE / 4) + 255) / 256, 256>>>(captions, emb);

    // ---- 3. vproj partials: spatial @ Wv^T, split-K x2 ----
    gemm_f16<<<dim3(1, 49, 2), 256, FSM>>>((fp16*)p_spf, DD, (fp16*)p_wvf, DD,
        nullptr, KK_, BQ * KK_, KK_, 256,
        nullptr, (float*)p_vpart, (long)BQ * KK_ * KK_, nullptr, 0);

    // ---- 4. gates_x = embseq_compact @ W_ih[:,:E]^T  (active rows only) ----
    gemm_f16<<<dim3(16, 20), 256, FSM>>>((fp16*)p_embf, EE, (fp16*)p_wihef, EE,
        (float*)p_gatesx, G4, BQ * TT, G4, EE,
        nullptr, nullptr, 0, (const int*)p_mact, 0);

    // ---- 5. init partials: global @ [Winit_h;Winit_m;W_ihD]^T, split-K x4 ----
    gemm_f16<<<dim3(24, 1, 4), 256, FSM>>>((fp16*)p_glf, DD, (fp16*)p_wcatf, DD,
        nullptr, 3072, BQ, 3072, 128,
        nullptr, (float*)p_ipart, (long)BQ * 3072, nullptr, 0);

    // ---- 6. recurrence (fp16 MMA, length-aware, compact s/gx) ----
    recur_kernel<<<136, 256, RSM>>>(b_hh, lengths, bg, wh, bh_att,
                                    b_init_h, b_init_m, b_ih, bv);

    // ---- 7. zero inactive output rows ----
    zfill<<<BQ * TT, 256>>>(lengths, out);

    // ---- 8. logits = s_compact @ Wp^T + bp, scattered via rmap ----
    gemm_f16<<<dim3(79, 20), 256, FSM>>>((fp16*)p_sf, DD, (fp16*)p_wpf, DD,
        out, VV, BQ * TT, VV, DD,
        bp, nullptr, 0, (const int*)p_mact, 1);
}

// round 12
// speedup vs baseline: 1.1561x; 1.1561x over previous
#include <cuda_runtime.h>
#include <cuda_fp16.h>
#include <math.h>
#include <stdint.h>

#define BQ  128
#define KK_ 49
#define DD  512
#define EE  256
#define VV  10000
#define TT  20
#define G4  2048
#define NW  2176          // padded gates+Wg width: 2048 + 49 -> 17*128
typedef __half fp16;

// -------------------- device scratch (static) --------------------
__device__ __align__(128) fp16 g_embf[BQ*TT*EE];
__device__ __align__(128) fp16 g_glf[BQ*DD];
__device__ __align__(128) fp16 g_wihef[G4*EE];
__device__ __align__(128) fp16 g_wcatf[3072*DD];   // [Winit_h;Winit_m;W_ih_D]
__device__ __align__(128) fp16 g_wc2f[NW*DD];      // [W_hh;Wg;0pad]
__device__ __align__(128) fp16 g_wvf[KK_*DD];
__device__ __align__(128) fp16 g_wpf[VV*DD];
__device__ __align__(128) fp16 g_spf[BQ*KK_*DD];
__device__ __align__(128) fp16 g_hf[BQ*DD];
__device__ __align__(128) fp16 g_sf[BQ*TT*DD];     // compacted active rows
__device__ __align__(128) float g_gatesx[BQ*TT*G4];// compacted active rows
__device__ __align__(128) float g_vproj[BQ*KK_*KK_];
__device__ __align__(128) float g_part[BQ*8*NW];
__device__ __align__(128) float g_ipart[4][BQ*3072];
__device__ __align__(128) float g_vpart[2][BQ*KK_*KK_];
__device__ int g_rmap[BQ*TT];     // compact row -> b*TT+t
__device__ int g_mact;            // number of active rows
__device__ unsigned g_bgrp[17];   // 2-level barrier group counters (monotonic)
__device__ unsigned g_brt;        // root counter (monotonic)
__device__ unsigned g_bgen;       // generation (monotonic)

// -------------------- helpers --------------------
__device__ __forceinline__ uint32_t su(const void* p) {
    return (uint32_t)__cvta_generic_to_shared(p);
}
__device__ __forceinline__ void cpa16(uint32_t sa, const void* ga, uint32_t sz) {
    asm volatile("cp.async.cg.shared.global [%0],[%1],16,%2;\n" :: "r"(sa), "l"(ga), "r"(sz));
}
__device__ __forceinline__ void cpcommit() { asm volatile("cp.async.commit_group;\n"); }
template<int N> __device__ __forceinline__ void cpwait() {
    asm volatile("cp.async.wait_group %0;\n" :: "n"(N));
}
__device__ __forceinline__ void ldsm4(uint32_t* r, uint32_t a) {
    asm volatile("ldmatrix.sync.aligned.m8n8.x4.shared.b16 {%0,%1,%2,%3},[%4];\n"
                 : "=r"(r[0]), "=r"(r[1]), "=r"(r[2]), "=r"(r[3]) : "r"(a));
}
__device__ __forceinline__ void mmah(float* c, const uint32_t* a, uint32_t b0, uint32_t b1) {
    asm volatile(
        "mma.sync.aligned.m16n8k16.row.col.f32.f16.f16.f32 "
        "{%0,%1,%2,%3},{%4,%5,%6,%7},{%8,%9},{%0,%1,%2,%3};\n"
        : "+f"(c[0]), "+f"(c[1]), "+f"(c[2]), "+f"(c[3])
        : "r"(a[0]), "r"(a[1]), "r"(a[2]), "r"(a[3]), "r"(b0), "r"(b1));
}
__device__ __forceinline__ float fsig(float x) { return 1.f / (1.f + __expf(-x)); }
__device__ __forceinline__ float ftanh(float x) {
    float e = __expf(2.f * x);
    return 1.f - 2.f / (e + 1.f);
}

// -------------------- fp32 -> fp16 segmented converter --------------------
struct Seg { const float4* src; uint2* dst; int srcld4; int lc4; long long start; };
struct SegArr { Seg s[10]; long long total; };

__global__ void conv_all(SegArr sa) {
    long long i = (long long)blockIdx.x * blockDim.x + threadIdx.x;
    if (i >= sa.total) return;
    int k = 0;
#pragma unroll
    for (int j = 1; j < 10; j++) if (i >= sa.s[j].start) k = j;
    Seg sg = sa.s[k];
    long long idx = i - sg.start;
    int row = (int)(idx >> sg.lc4);
    int c   = (int)(idx & ((1 << sg.lc4) - 1));
    float4 v = sg.src[(long long)row * sg.srcld4 + c];
    __half2 a = __floats2half2_rn(v.x, v.y);
    __half2 b = __floats2half2_rn(v.z, v.w);
    uint2 o;
    o.x = *reinterpret_cast<uint32_t*>(&a);
    o.y = *reinterpret_cast<uint32_t*>(&b);
    sg.dst[idx] = o;
}

// -------------------- active-row map --------------------
__global__ void build_map(const int* __restrict__ lengths) {
    __shared__ int cnt[20], off[21];
    int tid = threadIdx.x;
    if (tid < 20) {
        int c = 0;
        for (int b = 0; b < BQ; b++) c += (lengths[b] > tid);
        cnt[tid] = c;
    }
    __syncthreads();
    if (tid == 0) {
        off[0] = 0;
        for (int t = 0; t < 20; t++) off[t + 1] = off[t] + cnt[t];
        g_mact = off[20];
    }
    __syncthreads();
    for (int t = 0; t < 20; t++)
        for (int b = tid; b < cnt[t]; b += 256)
            g_rmap[off[t] + b] = b * TT + t;
}

// -------------------- zero-fill inactive output rows --------------------
__global__ void zfill(const int* __restrict__ lengths, float* __restrict__ out) {
    int row = blockIdx.x;
    int b = row / TT, t = row % TT;
    if (lengths[b] > t) return;
    float4 z = make_float4(0.f, 0.f, 0.f, 0.f);
    float4* o = reinterpret_cast<float4*>(out + (size_t)row * VV);
    for (int i = threadIdx.x; i < VV / 4; i += 256) o[i] = z;
}

// -------------------- embedding gather (compact, fp16) --------------------
__global__ void gather_emb(const int* __restrict__ cap, const float* __restrict__ emb) {
    int i = blockIdx.x * blockDim.x + threadIdx.x;
    if (i >= BQ * TT * (EE / 4)) return;
    int r = i >> 6, e4 = i & 63;
    if (r >= g_mact) return;
    int tok = cap[g_rmap[r]];
    float4 v = reinterpret_cast<const float4*>(emb)[(size_t)tok * 64 + e4];
    __half2 a = __floats2half2_rn(v.x, v.y);
    __half2 b = __floats2half2_rn(v.z, v.w);
    uint2 o;
    o.x = *reinterpret_cast<uint32_t*>(&a);
    o.y = *reinterpret_cast<uint32_t*>(&b);
    reinterpret_cast<uint2*>(g_embf)[(size_t)r * 64 + e4] = o;
}

// -------------------- generalized fp16 GEMM (128x128, 2-stage pipeline) --------------
// C[M,N] = A[M,K]@B[N,K]^T (+bias, optional split-K z, optional compact row map)
#define SST   40
#define FMATB (128 * SST)

__global__ void __launch_bounds__(256, 2) gemm_f16(
    const fp16* __restrict__ A, int lda,
    const fp16* __restrict__ B, int ldb,
    float* __restrict__ C, int ldc, int M, int N, int K,   // K = per-z slice
    const float* __restrict__ bias,
    float* __restrict__ Cpart, long partStride,
    const int* __restrict__ useMact,     // if set: M = g_mact (device), early-exit
    int useRmap)                         // if set: epilogue row = g_rmap[gm]
{
    int Meff = M;
    if (useMact) { Meff = g_mact; if (blockIdx.y * 128 >= Meff) return; }

    extern __shared__ __align__(16) char smraw[];
    fp16* sm = (fp16*)smraw;                     // [2][2][FMATB]

    const int tid = threadIdx.x;
    const int bm = blockIdx.y * 128, bn = blockIdx.x * 128;
    const int kz = blockIdx.z;
    float* Cw = Cpart ? (Cpart + (size_t)kz * partStride) : C;

    const int w = tid >> 5, lane = tid & 31;
    const int wm = w >> 2, wn = w & 3;
    const int g = lane >> 2, tg = lane & 3;
    const int lrow = lane & 15, lcol = (lane >> 4) * 8;
    const int ldrow = tid >> 1, ldch = (tid & 1) * 2;

    const fp16* aSrc = A + (size_t)kz * K + (size_t)(bm + ldrow) * lda + ldch * 8;
    int gn_l = bn + ldrow;
    uint32_t szb = (gn_l < N) ? 16u : 0u;
    if (gn_l >= N) gn_l = 0;
    const fp16* bSrc = B + (size_t)kz * K + (size_t)gn_l * ldb + ldch * 8;
    const uint32_t da = su(sm + ldrow * SST + ldch * 8);
    const uint32_t db = da + FMATB * 2;

    float acc[4][4][4];
#pragma unroll
    for (int i = 0; i < 4; i++)
#pragma unroll
        for (int j = 0; j < 4; j++)
#pragma unroll
            for (int q = 0; q < 4; q++) acc[i][j][q] = 0.f;

    auto issue = [&](int stg, int k0) {
        uint32_t so = (uint32_t)(stg * 2 * FMATB) * 2;
        cpa16(da + so,      aSrc + k0,     16);
        cpa16(da + so + 16, aSrc + k0 + 8, 16);
        cpa16(db + so,      bSrc + k0,     szb);
        cpa16(db + so + 16, bSrc + k0 + 8, szb);
    };

    const int niter = K / 32;
    issue(0, 0);
    cpcommit();
    int st = 0;
    for (int it = 0; it < niter; ++it) {
        if (it + 1 < niter) {
            issue(st ^ 1, (it + 1) * 32);
            cpcommit();
            cpwait<1>();
        } else {
            cpwait<0>();
        }
        __syncthreads();
        const fp16* base = sm + st * 2 * FMATB;
#pragma unroll
        for (int ks = 0; ks < 32; ks += 16) {
            uint32_t ah[4][4], bh[2][4];
#pragma unroll
            for (int mi = 0; mi < 4; mi++)
                ldsm4(ah[mi], su(base + (wm * 64 + mi * 16 + lrow) * SST + ks + lcol));
#pragma unroll
            for (int p = 0; p < 2; p++)
                ldsm4(bh[p], su(base + FMATB + (wn * 32 + p * 16 + lrow) * SST + ks + lcol));
#pragma unroll
            for (int mi = 0; mi < 4; mi++)
#pragma unroll
                for (int ni = 0; ni < 4; ni++) {
                    const int p = ni >> 1, q = ni & 1;
                    mmah(acc[mi][ni], ah[mi], bh[p][q], bh[p][q + 2]);
                }
        }
        __syncthreads();
        st ^= 1;
    }

#pragma unroll
    for (int mi = 0; mi < 4; mi++)
#pragma unroll
        for (int ni = 0; ni < 4; ni++) {
            int gn0 = bn + wn * 32 + ni * 8 + tg * 2;
#pragma unroll
            for (int half = 0; half < 2; half++) {
                int gm = bm + wm * 64 + mi * 16 + g + half * 8;
                if (gm >= Meff) continue;
                int orow = useRmap ? g_rmap[gm] : gm;
#pragma unroll
                for (int q = 0; q < 2; q++) {
                    int gn = gn0 + q;
                    if (gn >= N) continue;
                    float v = acc[mi][ni][half * 2 + q];
                    if (bias) v += bias[gn];
                    Cw[(size_t)orow * ldc + gn] = v;
                }
            }
        }
}

// -------------------- 2-level grid barrier (monotonic, replay-safe) --------------------
__device__ __forceinline__ void gridbar2(int grp, unsigned rr) {
    __syncthreads();
    if (threadIdx.x == 0) {
        unsigned old;
        asm volatile("atom.add.release.gpu.u32 %0,[%1],1;"
                     : "=r"(old) : "l"(&g_bgrp[grp]) : "memory");
        if (old == rr * 8u + 7u) {
            unsigned old2;
            asm volatile("atom.add.release.gpu.u32 %0,[%1],1;"
                         : "=r"(old2) : "l"(&g_brt) : "memory");
            if (old2 == rr * 17u + 16u) {
                asm volatile("st.release.gpu.u32 [%0],%1;"
                             :: "l"(&g_bgen), "r"(rr + 1u) : "memory");
            }
        }
        unsigned v;
        do {
            asm volatile("ld.acquire.gpu.u32 %0,[%1];"
                         : "=r"(v) : "l"(&g_bgen) : "memory");
        } while ((int)(v - (rr + 1u)) < 0);
    }
    __syncthreads();
}

// -------------------- persistent recurrence kernel (fp16 MMA) --------------------
#define RST 72
#define RMATB (128 * RST)

__global__ __launch_bounds__(256, 1) void recur_kernel(
    const float* __restrict__ b_hh,
    const int*   __restrict__ lengths,
    const float* __restrict__ bg,
    const float* __restrict__ wh,
    const float* __restrict__ bh_att,
    const float* __restrict__ b_init_h,
    const float* __restrict__ b_init_m,
    const float* __restrict__ b_ih,
    const float* __restrict__ bv)
{
    extern __shared__ __align__(16) char dsm[];
    fp16* sA = (fp16*)dsm;             // [128][RST]
    fp16* sB = sA + RMATB;             // [128][RST]
    float* sh_gh    = (float*)(dsm + 2 * RMATB * 2);
    float* sh_z     = sh_gh + 52;
    float* sh_alpha = sh_z + 52;
    int*   rs_cnt   = (int*)(sh_alpha + 52);   // [21]
    int*   rs_off   = rs_cnt + 21;             // [22]

    const int c = blockIdx.x;
    const int tid = threadIdx.x;
    const int kc = c & 7, cg = c >> 3, kbase = kc * 64;   // cg in 0..16
    const int grp = cg;
    const int b = c;                                      // phase2 owner (b<128)
    const int w = tid >> 5, lane = tid & 31;
    const int wm = w >> 2, wn = w & 3;
    const int g = lane >> 2, tg = lane & 3;
    const int lrow = lane & 15, lcol = (lane >> 4) * 8;
    const int wid = w;
    const float bh0 = bh_att[0];

    unsigned rbase;
    asm volatile("ld.acquire.gpu.u32 %0,[%1];" : "=r"(rbase) : "l"(&g_bgen) : "memory");
    unsigned round = 0;

    float hp[2], mr[2], gb[8];
    int len = 0;

    // ---- prologue: cnt/off arrays + per-batch init reduce + W slice preload ----
    if (tid < 21) {
        int cc = 0;
        for (int bb = 0; bb < BQ; bb++) cc += (lengths[bb] > tid);
        rs_cnt[tid] = cc;
    }
    __syncthreads();
    if (tid == 0) {
        rs_off[0] = 0;
        for (int u = 0; u < 21; u++) rs_off[u + 1] = rs_off[u] + rs_cnt[u];
    }
    __syncthreads();

    if (b < BQ) {
        len = lengths[b];
#pragma unroll
        for (int j = 0; j < 12; j++) {
            int n = tid + j * 256;
            float v = g_ipart[0][b * 3072 + n] + g_ipart[1][b * 3072 + n]
                    + g_ipart[2][b * 3072 + n] + g_ipart[3][b * 3072 + n];
            if (j < 2) {
                v += b_init_h[n];
                hp[j] = v;
                g_hf[b * DD + n] = __float2half(v);
            } else if (j < 4) {
                mr[j - 2] = v + b_init_m[n - 512];
            } else {
                int col = n - 1024;
                gb[j - 4] = v + b_ih[col] + b_hh[col];
            }
        }
        for (int i = tid; i < KK_ * KK_; i += 256) {
            int r = b * KK_ + i / KK_, q = i % KK_;
            g_vproj[(size_t)r * KK_ + q] =
                g_vpart[0][(size_t)r * KK_ + q] + g_vpart[1][(size_t)r * KK_ + q] + bv[q];
        }
    }
#pragma unroll
    for (int j = 0; j < 4; j++) {
        int cid = tid + j * 256;
        int row = cid >> 3, ch = cid & 7;
        *(float4*)(sB + row * RST + ch * 8) =
            *(const float4*)(g_wc2f + (size_t)(cg * 128 + row) * DD + kbase + ch * 8);
    }
    gridbar2(grp, rbase + round); round++;

    for (int t = 0; t <= TT; t++) {
        // ---------------- GEMM: [gates(t); gh(t-1)] = h(t-1) @ W_cat^T ----------------
        {
#pragma unroll
            for (int j = 0; j < 4; j++) {
                int cid = tid + j * 256;
                int row = cid >> 3, ch = cid & 7;
                *(float4*)(sA + row * RST + ch * 8) =
                    *(const float4*)(g_hf + (size_t)row * DD + kbase + ch * 8);
            }
            __syncthreads();

            float acc[4][4][4];
#pragma unroll
            for (int i = 0; i < 4; i++)
#pragma unroll
                for (int j = 0; j < 4; j++)
#pragma unroll
                    for (int q = 0; q < 4; q++) acc[i][j][q] = 0.f;

#pragma unroll
            for (int ks = 0; ks < 64; ks += 16) {
                uint32_t ah[4][4], bh2[2][4];
#pragma unroll
                for (int mi = 0; mi < 4; mi++)
                    ldsm4(ah[mi], su(sA + (wm * 64 + mi * 16 + lrow) * RST + ks + lcol));
#pragma unroll
                for (int p = 0; p < 2; p++)
                    ldsm4(bh2[p], su(sB + (wn * 32 + p * 16 + lrow) * RST + ks + lcol));
#pragma unroll
                for (int mi = 0; mi < 4; mi++)
#pragma unroll
                    for (int ni = 0; ni < 4; ni++) {
                        const int p = ni >> 1, q = ni & 1;
                        mmah(acc[mi][ni], ah[mi], bh2[p][q], bh2[p][q + 2]);
                    }
            }

#pragma unroll
            for (int mi = 0; mi < 4; mi++)
#pragma unroll
                for (int ni = 0; ni < 4; ni++) {
                    int gn0 = wn * 32 + ni * 8 + tg * 2;
#pragma unroll
                    for (int half = 0; half < 2; half++) {
                        int gm = wm * 64 + mi * 16 + g + half * 8;   // batch row
                        float* pr = g_part + (size_t)gm * (8 * NW) + kc * NW + cg * 128 + gn0;
                        pr[0] = acc[mi][ni][half * 2 + 0];
                        pr[1] = acc[mi][ni][half * 2 + 1];
                    }
                }
        }
        gridbar2(grp, rbase + round); round++;
        // ---------------- phase 2 (CTA b < 128) ----------------
        if (b < BQ) {
            const float* pp = g_part + (size_t)b * (8 * NW);
            // ---- attention for step t-1 ----
            if (t >= 1 && len > t - 1) {
                if (tid < KK_) {
                    float s = bg[tid];
#pragma unroll
                    for (int q = 0; q < 8; q++) s += pp[q * NW + 2048 + tid];
                    sh_gh[tid] = s;
                }
                __syncthreads();
                for (int k = wid; k < KK_; k += 8) {
                    const float* vp = g_vproj + (size_t)(b * KK_ + k) * KK_;
                    float s = 0.f;
                    for (int q = lane; q < KK_; q += 32) s += ftanh(vp[q] + sh_gh[q]) * wh[q];
#pragma unroll
                    for (int o = 16; o; o >>= 1) s += __shfl_xor_sync(0xffffffffu, s, o);
                    if (lane == 0) sh_z[k] = s + bh0;
                }
                __syncthreads();
                if (wid == 0) {
                    float mx = -3.0e38f;
                    for (int k = lane; k < KK_; k += 32) mx = fmaxf(mx, sh_z[k]);
#pragma unroll
                    for (int o = 16; o; o >>= 1) mx = fmaxf(mx, __shfl_xor_sync(0xffffffffu, mx, o));
                    float sm = 0.f;
                    for (int k = lane; k < KK_; k += 32) { float e = __expf(sh_z[k] - mx); sh_alpha[k] = e; sm += e; }
#pragma unroll
                    for (int o = 16; o; o >>= 1) sm += __shfl_xor_sync(0xffffffffu, sm, o);
                    float inv = 1.f / sm;
                    for (int k = lane; k < KK_; k += 32) sh_alpha[k] *= inv;
                }
                __syncthreads();
                const fp16* sp = g_spf + (size_t)b * KK_ * DD;
                const int spos = rs_off[t - 1] + b;      // compact row for (b, t-1)
#pragma unroll
                for (int j = 0; j < 2; j++) {
                    int d = tid + j * 256;
                    float cc = 0.f;
#pragma unroll
                    for (int k = 0; k < KK_; k++)
                        cc = fmaf(sh_alpha[k], __half2float(sp[(size_t)k * DD + d]), cc);
                    float sv = cc + hp[j];
                    g_sf[(size_t)spos * DD + d] = __float2half(sv);
                }
            }
            // ---- LSTM for step t ----
            if (t < TT && len > t) {
                const float* gx = g_gatesx + (size_t)(rs_off[t] + b) * G4;   // compact
#pragma unroll
                for (int j = 0; j < 2; j++) {
                    int d = tid + j * 256;
                    float gi = gx[d]        + gb[j];
                    float gf = gx[512 + d]  + gb[2 + j];
                    float gg = gx[1024 + d] + gb[4 + j];
                    float go = gx[1536 + d] + gb[6 + j];
#pragma unroll
                    for (int q = 0; q < 8; q++) {
                        const float* p = pp + q * NW;
                        gi += p[d]; gf += p[512 + d]; gg += p[1024 + d]; go += p[1536 + d];
                    }
                    float ig = fsig(gi), fg = fsig(gf), og = fsig(go);
                    float gt = ftanh(gg);
                    float mn = fg * mr[j] + ig * gt;
                    float hv = og * ftanh(mn);
                    mr[j] = mn;
                    hp[j] = hv;
                    g_hf[(size_t)b * DD + d] = __float2half(hv);
                }
            }
        }
        gridbar2(grp, rbase + round); round++;
    }
}

// -------------------- launch --------------------
extern "C" void kernel_launch(void* const* d_in, const int* in_sizes, int n_in,
                              void* d_out, int out_size)
{
    const float* spatial      = (const float*)d_in[0];
    const float* global_feats = (const float*)d_in[1];
    const int*   captions     = (const int*)d_in[2];
    const int*   lengths      = (const int*)d_in[3];
    const float* emb          = (const float*)d_in[4];
    const float* W_init_h     = (const float*)d_in[5];
    const float* b_init_h     = (const float*)d_in[6];
    const float* W_init_m     = (const float*)d_in[7];
    const float* b_init_m     = (const float*)d_in[8];
    const float* W_ih         = (const float*)d_in[9];
    const float* b_ih         = (const float*)d_in[10];
    const float* W_hh         = (const float*)d_in[11];
    const float* b_hh         = (const float*)d_in[12];
    const float* Wv           = (const float*)d_in[13];
    const float* bv           = (const float*)d_in[14];
    const float* Wg           = (const float*)d_in[15];
    const float* bg           = (const float*)d_in[16];
    const float* wh           = (const float*)d_in[17];
    const float* bh_att       = (const float*)d_in[18];
    const float* Wp           = (const float*)d_in[19];
    const float* bp           = (const float*)d_in[20];
    float* out = (float*)d_out;

#define GETP(var, sym) void* var; cudaGetSymbolAddress(&var, sym)
    GETP(p_embf, g_embf);    GETP(p_glf, g_glf);
    GETP(p_wihef, g_wihef);  GETP(p_wcatf, g_wcatf);
    GETP(p_wc2f, g_wc2f);    GETP(p_wvf, g_wvf);
    GETP(p_wpf, g_wpf);      GETP(p_spf, g_spf);
    GETP(p_sf, g_sf);
    GETP(p_gatesx, g_gatesx);
    GETP(p_ipart, g_ipart);  GETP(p_vpart, g_vpart);
    GETP(p_mact, g_mact);
#undef GETP

    const int FSM = 2 * 2 * FMATB * 2;                       // 40960 B
    const int RSM = 2 * RMATB * 2 + (3 * 52) * 4 + 43 * 4 + 64;
    cudaFuncSetAttribute(gemm_f16, cudaFuncAttributeMaxDynamicSharedMemorySize, FSM);
    cudaFuncSetAttribute(recur_kernel, cudaFuncAttributeMaxDynamicSharedMemorySize, RSM);

    // ---- 0. active-row map ----
    build_map<<<1, 256>>>(lengths);

    // ---- 1. convert all fp32 operands to fp16 ----
    SegArr sa;
    long long pos = 0;
    auto seg = [&](int i, const float* src, void* dst, int srcld, int cols, int rows) {
        sa.s[i].src = (const float4*)src;
        sa.s[i].dst = (uint2*)dst;
        sa.s[i].srcld4 = srcld / 4;
        sa.s[i].lc4 = (cols / 4 == 64) ? 6 : 7;
        sa.s[i].start = pos;
        pos += (long long)rows * (cols / 4);
    };
    seg(0, global_feats, p_glf, DD, DD, BQ);
    seg(1, W_init_h, p_wcatf, DD, DD, DD);
    seg(2, W_init_m, (fp16*)p_wcatf + 512 * DD, DD, DD, DD);
    seg(3, W_ih, p_wihef, EE + DD, EE, G4);
    seg(4, W_ih + EE, (fp16*)p_wcatf + 1024 * DD, EE + DD, DD, G4);
    seg(5, W_hh, p_wc2f, DD, DD, G4);
    seg(6, Wg, (fp16*)p_wc2f + 2048 * DD, DD, DD, KK_);
    seg(7, Wv, p_wvf, DD, DD, KK_);
    seg(8, Wp, p_wpf, DD, DD, VV);
    seg(9, spatial, p_spf, DD, DD, BQ * KK_);
    sa.total = pos;
    conv_all<<<(unsigned)((pos + 255) / 256), 256>>>(sa);

    // ---- 2. gather caption embeddings (compact, fp16) ----
    gather_emb<<<(BQ * TT * (EE / 4) + 255) / 256, 256>>>(captions, emb);

    // ---- 3. vproj partials: spatial @ Wv^T, split-K x2 ----
    gemm_f16<<<dim3(1, 49, 2), 256, FSM>>>((fp16*)p_spf, DD, (fp16*)p_wvf, DD,
        nullptr, KK_, BQ * KK_, KK_, 256,
        nullptr, (float*)p_vpart, (long)BQ * KK_ * KK_, nullptr, 0);

    // ---- 4. gates_x = embseq_compact @ W_ih[:,:E]^T  (active rows only) ----
    gemm_f16<<<dim3(16, 20), 256, FSM>>>((fp16*)p_embf, EE, (fp16*)p_wihef, EE,
        (float*)p_gatesx, G4, BQ * TT, G4, EE,
        nullptr, nullptr, 0, (const int*)p_mact, 0);

    // ---- 5. init partials: global @ [Winit_h;Winit_m;W_ihD]^T, split-K x4 ----
    gemm_f16<<<dim3(24, 1, 4), 256, FSM>>>((fp16*)p_glf, DD, (fp16*)p_wcatf, DD,
        nullptr, 3072, BQ, 3072, 128,
        nullptr, (float*)p_ipart, (long)BQ * 3072, nullptr, 0);

    // ---- 6. recurrence (fp16 MMA, static GEMM, compact s/gx indexing) ----
    recur_kernel<<<136, 256, RSM>>>(b_hh, lengths, bg, wh, bh_att,
                                    b_init_h, b_init_m, b_ih, bv);

    // ---- 7. zero inactive output rows ----
    zfill<<<BQ * TT, 256>>>(lengths, out);

    // ---- 8. logits = s_compact @ Wp^T + bp, scattered via rmap ----
    gemm_f16<<<dim3(79, 20), 256, FSM>>>((fp16*)p_sf, DD, (fp16*)p_wpf, DD,
        out, VV, BQ * TT, VV, DD,
        bp, nullptr, 0, (const int*)p_mact, 1);
}

// round 13
// speedup vs baseline: 1.3560x; 1.1729x over previous
#include <cuda_runtime.h>
#include <cuda_fp16.h>
#include <math.h>
#include <stdint.h>

#define BQ  128
#define KK_ 49
#define DD  512
#define EE  256
#define VV  10000
#define TT  20
#define G4  2048
#define NW  2176          // padded gates+Wg width: 2048 + 49 -> 17*128
#define PODS 8
typedef __half fp16;

// -------------------- device scratch (static) --------------------
__device__ __align__(128) fp16 g_embf[BQ*TT*EE];
__device__ __align__(128) fp16 g_glf[BQ*DD];
__device__ __align__(128) fp16 g_wihef[G4*EE];
__device__ __align__(128) fp16 g_wcatf[3072*DD];   // [Winit_h;Winit_m;W_ih_D]
__device__ __align__(128) fp16 g_wc2f[NW*DD];      // [W_hh;Wg;0pad]
__device__ __align__(128) fp16 g_wvf[KK_*DD];
__device__ __align__(128) fp16 g_wpf[VV*DD];
__device__ __align__(128) fp16 g_spf[BQ*KK_*DD];
__device__ __align__(128) fp16 g_hf[BQ*DD];
__device__ __align__(128) fp16 g_sf[BQ*TT*DD];     // compacted active rows
__device__ __align__(128) float g_gatesx[BQ*TT*G4];// compacted active rows
__device__ __align__(128) float g_vproj[BQ*KK_*KK_];
__device__ __align__(128) float g_g2[BQ*NW];       // gates+gh rows (no split-K)
__device__ __align__(128) float g_ipart[4][BQ*3072];
__device__ __align__(128) float g_vpart[2][BQ*KK_*KK_];
__device__ int g_rmap[BQ*TT];     // compact row -> b*TT+t
__device__ int g_mact;            // number of active rows
__device__ unsigned g_pbar[PODS][32];   // pod barrier counters (monotonic)
__device__ unsigned g_pgen[PODS][32];   // pod generations (monotonic)

// -------------------- helpers --------------------
__device__ __forceinline__ uint32_t su(const void* p) {
    return (uint32_t)__cvta_generic_to_shared(p);
}
__device__ __forceinline__ void cpa16(uint32_t sa, const void* ga, uint32_t sz) {
    asm volatile("cp.async.cg.shared.global [%0],[%1],16,%2;\n" :: "r"(sa), "l"(ga), "r"(sz));
}
__device__ __forceinline__ void cpcommit() { asm volatile("cp.async.commit_group;\n"); }
template<int N> __device__ __forceinline__ void cpwait() {
    asm volatile("cp.async.wait_group %0;\n" :: "n"(N));
}
__device__ __forceinline__ void ldsm4(uint32_t* r, uint32_t a) {
    asm volatile("ldmatrix.sync.aligned.m8n8.x4.shared.b16 {%0,%1,%2,%3},[%4];\n"
                 : "=r"(r[0]), "=r"(r[1]), "=r"(r[2]), "=r"(r[3]) : "r"(a));
}
__device__ __forceinline__ void mmah(float* c, const uint32_t* a, uint32_t b0, uint32_t b1) {
    asm volatile(
        "mma.sync.aligned.m16n8k16.row.col.f32.f16.f16.f32 "
        "{%0,%1,%2,%3},{%4,%5,%6,%7},{%8,%9},{%0,%1,%2,%3};\n"
        : "+f"(c[0]), "+f"(c[1]), "+f"(c[2]), "+f"(c[3])
        : "r"(a[0]), "r"(a[1]), "r"(a[2]), "r"(a[3]), "r"(b0), "r"(b1));
}
__device__ __forceinline__ float fsig(float x) { return 1.f / (1.f + __expf(-x)); }
__device__ __forceinline__ float ftanh(float x) {
    float e = __expf(2.f * x);
    return 1.f - 2.f / (e + 1.f);
}

// -------------------- fp32 -> fp16 segmented converter --------------------
struct Seg { const float4* src; uint2* dst; int srcld4; int lc4; long long start; };
struct SegArr { Seg s[10]; long long total; };

__global__ void conv_all(SegArr sa) {
    long long i = (long long)blockIdx.x * blockDim.x + threadIdx.x;
    if (i >= sa.total) return;
    int k = 0;
#pragma unroll
    for (int j = 1; j < 10; j++) if (i >= sa.s[j].start) k = j;
    Seg sg = sa.s[k];
    long long idx = i - sg.start;
    int row = (int)(idx >> sg.lc4);
    int c   = (int)(idx & ((1 << sg.lc4) - 1));
    float4 v = sg.src[(long long)row * sg.srcld4 + c];
    __half2 a = __floats2half2_rn(v.x, v.y);
    __half2 b = __floats2half2_rn(v.z, v.w);
    uint2 o;
    o.x = *reinterpret_cast<uint32_t*>(&a);
    o.y = *reinterpret_cast<uint32_t*>(&b);
    sg.dst[idx] = o;
}

// -------------------- active-row map --------------------
__global__ void build_map(const int* __restrict__ lengths) {
    __shared__ int cnt[20], off[21];
    int tid = threadIdx.x;
    if (tid < 20) {
        int c = 0;
        for (int b = 0; b < BQ; b++) c += (lengths[b] > tid);
        cnt[tid] = c;
    }
    __syncthreads();
    if (tid == 0) {
        off[0] = 0;
        for (int t = 0; t < 20; t++) off[t + 1] = off[t] + cnt[t];
        g_mact = off[20];
    }
    __syncthreads();
    for (int t = 0; t < 20; t++)
        for (int b = tid; b < cnt[t]; b += 256)
            g_rmap[off[t] + b] = b * TT + t;
}

// -------------------- zero-fill inactive output rows --------------------
__global__ void zfill(const int* __restrict__ lengths, float* __restrict__ out) {
    int row = blockIdx.x;
    int b = row / TT, t = row % TT;
    if (lengths[b] > t) return;
    float4 z = make_float4(0.f, 0.f, 0.f, 0.f);
    float4* o = reinterpret_cast<float4*>(out + (size_t)row * VV);
    for (int i = threadIdx.x; i < VV / 4; i += 256) o[i] = z;
}

// -------------------- embedding gather (compact, fp16) --------------------
__global__ void gather_emb(const int* __restrict__ cap, const float* __restrict__ emb) {
    int i = blockIdx.x * blockDim.x + threadIdx.x;
    if (i >= BQ * TT * (EE / 4)) return;
    int r = i >> 6, e4 = i & 63;
    if (r >= g_mact) return;
    int tok = cap[g_rmap[r]];
    float4 v = reinterpret_cast<const float4*>(emb)[(size_t)tok * 64 + e4];
    __half2 a = __floats2half2_rn(v.x, v.y);
    __half2 b = __floats2half2_rn(v.z, v.w);
    uint2 o;
    o.x = *reinterpret_cast<uint32_t*>(&a);
    o.y = *reinterpret_cast<uint32_t*>(&b);
    reinterpret_cast<uint2*>(g_embf)[(size_t)r * 64 + e4] = o;
}

// -------------------- generalized fp16 GEMM (128x128, 2-stage pipeline) --------------
#define SST   40
#define FMATB (128 * SST)

__global__ void __launch_bounds__(256, 2) gemm_f16(
    const fp16* __restrict__ A, int lda,
    const fp16* __restrict__ B, int ldb,
    float* __restrict__ C, int ldc, int M, int N, int K,   // K = per-z slice
    const float* __restrict__ bias,
    float* __restrict__ Cpart, long partStride,
    const int* __restrict__ useMact,     // if set: M = g_mact (device), early-exit
    int useRmap)                         // if set: epilogue row = g_rmap[gm]
{
    int Meff = M;
    if (useMact) { Meff = g_mact; if (blockIdx.y * 128 >= Meff) return; }

    extern __shared__ __align__(16) char smraw[];
    fp16* sm = (fp16*)smraw;                     // [2][2][FMATB]

    const int tid = threadIdx.x;
    const int bm = blockIdx.y * 128, bn = blockIdx.x * 128;
    const int kz = blockIdx.z;
    float* Cw = Cpart ? (Cpart + (size_t)kz * partStride) : C;

    const int w = tid >> 5, lane = tid & 31;
    const int wm = w >> 2, wn = w & 3;
    const int g = lane >> 2, tg = lane & 3;
    const int lrow = lane & 15, lcol = (lane >> 4) * 8;
    const int ldrow = tid >> 1, ldch = (tid & 1) * 2;

    const fp16* aSrc = A + (size_t)kz * K + (size_t)(bm + ldrow) * lda + ldch * 8;
    int gn_l = bn + ldrow;
    uint32_t szb = (gn_l < N) ? 16u : 0u;
    if (gn_l >= N) gn_l = 0;
    const fp16* bSrc = B + (size_t)kz * K + (size_t)gn_l * ldb + ldch * 8;
    const uint32_t da = su(sm + ldrow * SST + ldch * 8);
    const uint32_t db = da + FMATB * 2;

    float acc[4][4][4];
#pragma unroll
    for (int i = 0; i < 4; i++)
#pragma unroll
        for (int j = 0; j < 4; j++)
#pragma unroll
            for (int q = 0; q < 4; q++) acc[i][j][q] = 0.f;

    auto issue = [&](int stg, int k0) {
        uint32_t so = (uint32_t)(stg * 2 * FMATB) * 2;
        cpa16(da + so,      aSrc + k0,     16);
        cpa16(da + so + 16, aSrc + k0 + 8, 16);
        cpa16(db + so,      bSrc + k0,     szb);
        cpa16(db + so + 16, bSrc + k0 + 8, szb);
    };

    const int niter = K / 32;
    issue(0, 0);
    cpcommit();
    int st = 0;
    for (int it = 0; it < niter; ++it) {
        if (it + 1 < niter) {
            issue(st ^ 1, (it + 1) * 32);
            cpcommit();
            cpwait<1>();
        } else {
            cpwait<0>();
        }
        __syncthreads();
        const fp16* base = sm + st * 2 * FMATB;
#pragma unroll
        for (int ks = 0; ks < 32; ks += 16) {
            uint32_t ah[4][4], bh[2][4];
#pragma unroll
            for (int mi = 0; mi < 4; mi++)
                ldsm4(ah[mi], su(base + (wm * 64 + mi * 16 + lrow) * SST + ks + lcol));
#pragma unroll
            for (int p = 0; p < 2; p++)
                ldsm4(bh[p], su(base + FMATB + (wn * 32 + p * 16 + lrow) * SST + ks + lcol));
#pragma unroll
            for (int mi = 0; mi < 4; mi++)
#pragma unroll
                for (int ni = 0; ni < 4; ni++) {
                    const int p = ni >> 1, q = ni & 1;
                    mmah(acc[mi][ni], ah[mi], bh[p][q], bh[p][q + 2]);
                }
        }
        __syncthreads();
        st ^= 1;
    }

#pragma unroll
    for (int mi = 0; mi < 4; mi++)
#pragma unroll
        for (int ni = 0; ni < 4; ni++) {
            int gn0 = bn + wn * 32 + ni * 8 + tg * 2;
#pragma unroll
            for (int half = 0; half < 2; half++) {
                int gm = bm + wm * 64 + mi * 16 + g + half * 8;
                if (gm >= Meff) continue;
                int orow = useRmap ? g_rmap[gm] : gm;
#pragma unroll
                for (int q = 0; q < 2; q++) {
                    int gn = gn0 + q;
                    if (gn >= N) continue;
                    float v = acc[mi][ni][half * 2 + q];
                    if (bias) v += bias[gn];
                    Cw[(size_t)orow * ldc + gn] = v;
                }
            }
        }
}

// -------------------- pod barrier (17 CTAs, monotonic, replay-safe) --------------------
__device__ __forceinline__ void podbar(unsigned* cnt, unsigned* gen, unsigned rr) {
    __syncthreads();
    if (threadIdx.x == 0) {
        unsigned old;
        asm volatile("atom.add.release.gpu.u32 %0,[%1],1;"
                     : "=r"(old) : "l"(cnt) : "memory");
        if (old == rr * 17u + 16u) {
            asm volatile("st.release.gpu.u32 [%0],%1;"
                         :: "l"(gen), "r"(rr + 1u) : "memory");
        }
        unsigned v;
        do {
            asm volatile("ld.acquire.gpu.u32 %0,[%1];"
                         : "=r"(v) : "l"(gen) : "memory");
        } while ((int)(v - (rr + 1u)) < 0);
    }
    __syncthreads();
}

// -------------------- pod-decomposed recurrence kernel --------------------
// 8 pods x 17 CTAs. Pod p owns batches [16p,16p+16). CTA j of a pod computes
// gates cols [128j,128j+128) for its pod's 16 rows (full K=512, no split-K).
// Pod-local barriers only; pods run/exit independently (sorted lengths).
#define RST2 520
#define RSM2 ((128 + 16) * RST2 * 2 + 3 * 52 * 4 + 43 * 4 + 64)

__global__ __launch_bounds__(256, 1) void recur_kernel(
    const float* __restrict__ b_hh,
    const int*   __restrict__ lengths,
    const float* __restrict__ bg,
    const float* __restrict__ wh,
    const float* __restrict__ bh_att,
    const float* __restrict__ b_init_h,
    const float* __restrict__ b_init_m,
    const float* __restrict__ b_ih,
    const float* __restrict__ bv)
{
    extern __shared__ __align__(16) char dsm[];
    fp16* sB = (fp16*)dsm;                   // [128][RST2] W slice (persistent)
    fp16* sA = sB + 128 * RST2;              // [16][RST2]  pod h rows
    float* sh_gh    = (float*)(sA + 16 * RST2);
    float* sh_z     = sh_gh + 52;
    float* sh_alpha = sh_z + 52;
    int*   rs_cnt   = (int*)(sh_alpha + 52);   // [21]
    int*   rs_off   = rs_cnt + 21;             // [22]

    const int c = blockIdx.x;
    const int p = c / 17, j = c % 17;
    const int pb0 = p * 16;
    const int b = pb0 + j;                   // phase2 batch (j<16 only)
    const int tid = threadIdx.x;
    const int w = tid >> 5, lane = tid & 31;
    const int g = lane >> 2, tg = lane & 3;
    const int lrow = lane & 15, lcol = (lane >> 4) * 8;
    const int wid = w;
    const float bh0 = bh_att[0];

    unsigned* pcnt = &g_pbar[p][0];
    unsigned* pgen = &g_pgen[p][0];
    unsigned rbase;
    asm volatile("ld.acquire.gpu.u32 %0,[%1];" : "=r"(rbase) : "l"(pgen) : "memory");
    unsigned round = 0;

    // ---- rs arrays (compact offsets) ----
    if (tid < 21) {
        int cc = 0;
        for (int bb = 0; bb < BQ; bb++) cc += (lengths[bb] > tid);
        rs_cnt[tid] = cc;
    }
    __syncthreads();
    if (tid == 0) {
        rs_off[0] = 0;
        for (int u = 0; u < 21; u++) rs_off[u + 1] = rs_off[u] + rs_cnt[u];
    }
    __syncthreads();

    // ---- pod length (max over pod batches; no sortedness assumption) ----
    int pod_len = 0;
#pragma unroll
    for (int q = 0; q < 16; q++) {
        int l = lengths[pb0 + q];
        pod_len = l > pod_len ? l : pod_len;
    }

    float hp[2], mr[2], gb[8];
    int len = 0;

    // ---- prologue: per-batch init reduce (j<16) ----
    if (j < 16) {
        len = lengths[b];
#pragma unroll
        for (int jj = 0; jj < 12; jj++) {
            int n = tid + jj * 256;
            float v = g_ipart[0][b * 3072 + n] + g_ipart[1][b * 3072 + n]
                    + g_ipart[2][b * 3072 + n] + g_ipart[3][b * 3072 + n];
            if (jj < 2) {
                v += b_init_h[n];
                hp[jj] = v;
                g_hf[b * DD + n] = __float2half(v);
            } else if (jj < 4) {
                mr[jj - 2] = v + b_init_m[n - 512];
            } else {
                int col = n - 1024;
                gb[jj - 4] = v + b_ih[col] + b_hh[col];
            }
        }
        for (int i = tid; i < KK_ * KK_; i += 256) {
            int r = b * KK_ + i / KK_, q = i % KK_;
            g_vproj[(size_t)r * KK_ + q] =
                g_vpart[0][(size_t)r * KK_ + q] + g_vpart[1][(size_t)r * KK_ + q] + bv[q];
        }
    }
    // ---- preload W slice: rows [128j, 128j+128), K=512 ----
#pragma unroll
    for (int k = 0; k < 32; k++) {
        int cid = tid + k * 256;            // 0..8191
        int row = cid >> 6, ch = cid & 63;  // 64 float4 per row
        *(float4*)(sB + row * RST2 + ch * 8) =
            *(const float4*)(g_wc2f + (size_t)(j * 128 + row) * DD + ch * 8);
    }
    podbar(pcnt, pgen, rbase + round); round++;   // h0 + vproj visible pod-wide

    for (int t = 0; t <= pod_len; t++) {
        // ---------------- phase 1: gates rows = h_pod @ Wslice^T ----------------
        {
#pragma unroll
            for (int k = 0; k < 4; k++) {
                int cid = tid + k * 256;            // 0..1023
                int row = cid >> 6, ch = cid & 63;
                *(float4*)(sA + row * RST2 + ch * 8) =
                    *(const float4*)(g_hf + (size_t)(pb0 + row) * DD + ch * 8);
            }
            __syncthreads();

            float acc[2][4];
#pragma unroll
            for (int q = 0; q < 2; q++)
#pragma unroll
                for (int i = 0; i < 4; i++) acc[q][i] = 0.f;

#pragma unroll
            for (int ks = 0; ks < 512; ks += 16) {
                uint32_t a4[4], b4[4];
                ldsm4(a4, su(sA + lrow * RST2 + ks + lcol));
                ldsm4(b4, su(sB + (w * 16 + lrow) * RST2 + ks + lcol));
                mmah(acc[0], a4, b4[0], b4[2]);
                mmah(acc[1], a4, b4[1], b4[3]);
            }

#pragma unroll
            for (int q = 0; q < 2; q++) {
                int col = j * 128 + w * 16 + q * 8 + tg * 2;
                float* r0 = g_g2 + (size_t)(pb0 + g) * NW + col;
                float* r1 = g_g2 + (size_t)(pb0 + g + 8) * NW + col;
                r0[0] = acc[q][0]; r0[1] = acc[q][1];
                r1[0] = acc[q][2]; r1[1] = acc[q][3];
            }
        }
        podbar(pcnt, pgen, rbase + round); round++;
        // ---------------- phase 2 (j < 16) ----------------
        if (j < 16) {
            const float* grow = g_g2 + (size_t)b * NW;
            // ---- attention for step t-1 ----
            if (t >= 1 && len > t - 1) {
                if (tid < KK_) sh_gh[tid] = bg[tid] + grow[2048 + tid];
                __syncthreads();
                for (int k = wid; k < KK_; k += 8) {
                    const float* vp = g_vproj + (size_t)(b * KK_ + k) * KK_;
                    float s = 0.f;
                    for (int q = lane; q < KK_; q += 32) s += ftanh(vp[q] + sh_gh[q]) * wh[q];
#pragma unroll
                    for (int o = 16; o; o >>= 1) s += __shfl_xor_sync(0xffffffffu, s, o);
                    if (lane == 0) sh_z[k] = s + bh0;
                }
                __syncthreads();
                if (wid == 0) {
                    float mx = -3.0e38f;
                    for (int k = lane; k < KK_; k += 32) mx = fmaxf(mx, sh_z[k]);
#pragma unroll
                    for (int o = 16; o; o >>= 1) mx = fmaxf(mx, __shfl_xor_sync(0xffffffffu, mx, o));
                    float sm = 0.f;
                    for (int k = lane; k < KK_; k += 32) { float e = __expf(sh_z[k] - mx); sh_alpha[k] = e; sm += e; }
#pragma unroll
                    for (int o = 16; o; o >>= 1) sm += __shfl_xor_sync(0xffffffffu, sm, o);
                    float inv = 1.f / sm;
                    for (int k = lane; k < KK_; k += 32) sh_alpha[k] *= inv;
                }
                __syncthreads();
                const fp16* sp = g_spf + (size_t)b * KK_ * DD;
                const int spos = rs_off[t - 1] + b;
#pragma unroll
                for (int jj = 0; jj < 2; jj++) {
                    int d = tid + jj * 256;
                    float cc = 0.f;
#pragma unroll
                    for (int k = 0; k < KK_; k++)
                        cc = fmaf(sh_alpha[k], __half2float(sp[(size_t)k * DD + d]), cc);
                    float sv = cc + hp[jj];
                    g_sf[(size_t)spos * DD + d] = __float2half(sv);
                }
            }
            // ---- LSTM for step t ----
            if (t < TT && len > t) {
                const float* gx = g_gatesx + (size_t)(rs_off[t] + b) * G4;
#pragma unroll
                for (int jj = 0; jj < 2; jj++) {
                    int d = tid + jj * 256;
                    float gi = gx[d]        + gb[jj]     + grow[d];
                    float gf = gx[512 + d]  + gb[2 + jj] + grow[512 + d];
                    float gg = gx[1024 + d] + gb[4 + jj] + grow[1024 + d];
                    float go = gx[1536 + d] + gb[6 + jj] + grow[1536 + d];
                    float ig = fsig(gi), fg = fsig(gf), og = fsig(go);
                    float gt = ftanh(gg);
                    float mn = fg * mr[jj] + ig * gt;
                    float hv = og * ftanh(mn);
                    mr[jj] = mn;
                    hp[jj] = hv;
                    g_hf[(size_t)b * DD + d] = __float2half(hv);
                }
            }
        }
        if (t < pod_len) { podbar(pcnt, pgen, rbase + round); round++; }
    }
}

// -------------------- launch --------------------
extern "C" void kernel_launch(void* const* d_in, const int* in_sizes, int n_in,
                              void* d_out, int out_size)
{
    const float* spatial      = (const float*)d_in[0];
    const float* global_feats = (const float*)d_in[1];
    const int*   captions     = (const int*)d_in[2];
    const int*   lengths      = (const int*)d_in[3];
    const float* emb          = (const float*)d_in[4];
    const float* W_init_h     = (const float*)d_in[5];
    const float* b_init_h     = (const float*)d_in[6];
    const float* W_init_m     = (const float*)d_in[7];
    const float* b_init_m     = (const float*)d_in[8];
    const float* W_ih         = (const float*)d_in[9];
    const float* b_ih         = (const float*)d_in[10];
    const float* W_hh         = (const float*)d_in[11];
    const float* b_hh         = (const float*)d_in[12];
    const float* Wv           = (const float*)d_in[13];
    const float* bv           = (const float*)d_in[14];
    const float* Wg           = (const float*)d_in[15];
    const float* bg           = (const float*)d_in[16];
    const float* wh           = (const float*)d_in[17];
    const float* bh_att       = (const float*)d_in[18];
    const float* Wp           = (const float*)d_in[19];
    const float* bp           = (const float*)d_in[20];
    float* out = (float*)d_out;

#define GETP(var, sym) void* var; cudaGetSymbolAddress(&var, sym)
    GETP(p_embf, g_embf);    GETP(p_glf, g_glf);
    GETP(p_wihef, g_wihef);  GETP(p_wcatf, g_wcatf);
    GETP(p_wc2f, g_wc2f);    GETP(p_wvf, g_wvf);
    GETP(p_wpf, g_wpf);      GETP(p_spf, g_spf);
    GETP(p_sf, g_sf);
    GETP(p_gatesx, g_gatesx);
    GETP(p_ipart, g_ipart);  GETP(p_vpart, g_vpart);
    GETP(p_mact, g_mact);
#undef GETP

    const int FSM = 2 * 2 * FMATB * 2;                       // 40960 B
    cudaFuncSetAttribute(gemm_f16, cudaFuncAttributeMaxDynamicSharedMemorySize, FSM);
    cudaFuncSetAttribute(recur_kernel, cudaFuncAttributeMaxDynamicSharedMemorySize, RSM2);

    // ---- 0. active-row map ----
    build_map<<<1, 256>>>(lengths);

    // ---- 1. convert all fp32 operands to fp16 ----
    SegArr sa;
    long long pos = 0;
    auto seg = [&](int i, const float* src, void* dst, int srcld, int cols, int rows) {
        sa.s[i].src = (const float4*)src;
        sa.s[i].dst = (uint2*)dst;
        sa.s[i].srcld4 = srcld / 4;
        sa.s[i].lc4 = (cols / 4 == 64) ? 6 : 7;
        sa.s[i].start = pos;
        pos += (long long)rows * (cols / 4);
    };
    seg(0, global_feats, p_glf, DD, DD, BQ);
    seg(1, W_init_h, p_wcatf, DD, DD, DD);
    seg(2, W_init_m, (fp16*)p_wcatf + 512 * DD, DD, DD, DD);
    seg(3, W_ih, p_wihef, EE + DD, EE, G4);
    seg(4, W_ih + EE, (fp16*)p_wcatf + 1024 * DD, EE + DD, DD, G4);
    seg(5, W_hh, p_wc2f, DD, DD, G4);
    seg(6, Wg, (fp16*)p_wc2f + 2048 * DD, DD, DD, KK_);
    seg(7, Wv, p_wvf, DD, DD, KK_);
    seg(8, Wp, p_wpf, DD, DD, VV);
    seg(9, spatial, p_spf, DD, DD, BQ * KK_);
    sa.total = pos;
    conv_all<<<(unsigned)((pos + 255) / 256), 256>>>(sa);

    // ---- 2. gather caption embeddings (compact, fp16) ----
    gather_emb<<<(BQ * TT * (EE / 4) + 255) / 256, 256>>>(captions, emb);

    // ---- 3. vproj partials: spatial @ Wv^T, split-K x2 ----
    gemm_f16<<<dim3(1, 49, 2), 256, FSM>>>((fp16*)p_spf, DD, (fp16*)p_wvf, DD,
        nullptr, KK_, BQ * KK_, KK_, 256,
        nullptr, (float*)p_vpart, (long)BQ * KK_ * KK_, nullptr, 0);

    // ---- 4. gates_x = embseq_compact @ W_ih[:,:E]^T  (active rows only) ----
    gemm_f16<<<dim3(16, 20), 256, FSM>>>((fp16*)p_embf, EE, (fp16*)p_wihef, EE,
        (float*)p_gatesx, G4, BQ * TT, G4, EE,
        nullptr, nullptr, 0, (const int*)p_mact, 0);

    // ---- 5. init partials: global @ [Winit_h;Winit_m;W_ihD]^T, split-K x4 ----
    gemm_f16<<<dim3(24, 1, 4), 256, FSM>>>((fp16*)p_glf, DD, (fp16*)p_wcatf, DD,
        nullptr, 3072, BQ, 3072, 128,
        nullptr, (float*)p_ipart, (long)BQ * 3072, nullptr, 0);

    // ---- 6. recurrence (pod-decomposed, pod-local barriers) ----
    recur_kernel<<<136, 256, RSM2>>>(b_hh, lengths, bg, wh, bh_att,
                                     b_init_h, b_init_m, b_ih, bv);

    // ---- 7. zero inactive output rows ----
    zfill<<<BQ * TT, 256>>>(lengths, out);

    // ---- 8. logits = s_compact @ Wp^T + bp, scattered via rmap ----
    gemm_f16<<<dim3(79, 20), 256, FSM>>>((fp16*)p_sf, DD, (fp16*)p_wpf, DD,
        out, VV, BQ * TT, VV, DD,
        bp, nullptr, 0, (const int*)p_mact, 1);
}

// round 14
// speedup vs baseline: 1.4965x; 1.1037x over previous
#include <cuda_runtime.h>
#include <cuda_fp16.h>
#include <math.h>
#include <stdint.h>

#define BQ  128
#define KK_ 49
#define DD  512
#define EE  256
#define VV  10000
#define TT  20
#define G4  2048
#define NW  2176          // padded gates+Wg width: 2048 + 49 -> 17*128
#define PODS 8
typedef __half fp16;

// -------------------- device scratch (static) --------------------
__device__ __align__(128) fp16 g_embf[BQ*TT*EE];
__device__ __align__(128) fp16 g_glf[BQ*DD];
__device__ __align__(128) fp16 g_wihef[G4*EE];
__device__ __align__(128) fp16 g_wcatf[3072*DD];   // [Winit_h;Winit_m;W_ih_D]
__device__ __align__(128) fp16 g_wc2f[NW*DD];      // [W_hh;Wg;0pad]
__device__ __align__(128) fp16 g_wvf[KK_*DD];
__device__ __align__(128) fp16 g_wpf[VV*DD];
__device__ __align__(128) fp16 g_spf[BQ*KK_*DD];
__device__ __align__(128) fp16 g_hf[BQ*DD];
__device__ __align__(128) fp16 g_sf[BQ*TT*DD];     // compacted active rows
__device__ __align__(128) float g_gatesx[BQ*TT*G4];// compacted active rows
__device__ __align__(128) float g_vproj[BQ*KK_*KK_];
__device__ __align__(128) float g_g2[BQ*NW];       // gates+gh rows
__device__ __align__(128) float g_ipart[4][BQ*3072];
__device__ __align__(128) float g_vpart[2][BQ*KK_*KK_];
__device__ int g_rmap[BQ*TT];     // compact row -> b*TT+t
__device__ int g_mact;            // number of active rows
__device__ unsigned g_pbar[PODS][32];   // pod barrier counters (monotonic)
__device__ unsigned g_pgen[PODS][32];   // pod generations (monotonic)

// -------------------- helpers --------------------
__device__ __forceinline__ uint32_t su(const void* p) {
    return (uint32_t)__cvta_generic_to_shared(p);
}
__device__ __forceinline__ void cpa16(uint32_t sa, const void* ga, uint32_t sz) {
    asm volatile("cp.async.cg.shared.global [%0],[%1],16,%2;\n" :: "r"(sa), "l"(ga), "r"(sz));
}
__device__ __forceinline__ void cpcommit() { asm volatile("cp.async.commit_group;\n"); }
template<int N> __device__ __forceinline__ void cpwait() {
    asm volatile("cp.async.wait_group %0;\n" :: "n"(N));
}
__device__ __forceinline__ void ldsm4(uint32_t* r, uint32_t a) {
    asm volatile("ldmatrix.sync.aligned.m8n8.x4.shared.b16 {%0,%1,%2,%3},[%4];\n"
                 : "=r"(r[0]), "=r"(r[1]), "=r"(r[2]), "=r"(r[3]) : "r"(a));
}
__device__ __forceinline__ void mmah(float* c, const uint32_t* a, uint32_t b0, uint32_t b1) {
    asm volatile(
        "mma.sync.aligned.m16n8k16.row.col.f32.f16.f16.f32 "
        "{%0,%1,%2,%3},{%4,%5,%6,%7},{%8,%9},{%0,%1,%2,%3};\n"
        : "+f"(c[0]), "+f"(c[1]), "+f"(c[2]), "+f"(c[3])
        : "r"(a[0]), "r"(a[1]), "r"(a[2]), "r"(a[3]), "r"(b0), "r"(b1));
}
__device__ __forceinline__ float fsig(float x) { return 1.f / (1.f + __expf(-x)); }
__device__ __forceinline__ float ftanh(float x) {
    float e = __expf(2.f * x);
    return 1.f - 2.f / (e + 1.f);
}

// -------------------- shared fp16 GEMM body (128x128 tile, 2-stage) --------------------
#define SST   40
#define FMATB (128 * SST)

__device__ __forceinline__ void gemm_body(
    const fp16* __restrict__ A, int lda,
    const fp16* __restrict__ B, int ldb,
    float* __restrict__ C, int ldc,
    int Meff, int N, int K, int bm, int bn,
    const float* __restrict__ bias, int useRmap, char* smraw)
{
    fp16* sm = (fp16*)smraw;                     // [2][2][FMATB]
    const int tid = threadIdx.x;
    const int w = tid >> 5, lane = tid & 31;
    const int wm = w >> 2, wn = w & 3;
    const int g = lane >> 2, tg = lane & 3;
    const int lrow = lane & 15, lcol = (lane >> 4) * 8;
    const int ldrow = tid >> 1, ldch = (tid & 1) * 2;

    const fp16* aSrc = A + (size_t)(bm + ldrow) * lda + ldch * 8;
    int gn_l = bn + ldrow;
    uint32_t szb = (gn_l < N) ? 16u : 0u;
    if (gn_l >= N) gn_l = 0;
    const fp16* bSrc = B + (size_t)gn_l * ldb + ldch * 8;
    const uint32_t da = su(sm + ldrow * SST + ldch * 8);
    const uint32_t db = da + FMATB * 2;

    float acc[4][4][4];
#pragma unroll
    for (int i = 0; i < 4; i++)
#pragma unroll
        for (int j = 0; j < 4; j++)
#pragma unroll
            for (int q = 0; q < 4; q++) acc[i][j][q] = 0.f;

    auto issue = [&](int stg, int k0) {
        uint32_t so = (uint32_t)(stg * 2 * FMATB) * 2;
        cpa16(da + so,      aSrc + k0,     16);
        cpa16(da + so + 16, aSrc + k0 + 8, 16);
        cpa16(db + so,      bSrc + k0,     szb);
        cpa16(db + so + 16, bSrc + k0 + 8, szb);
    };

    const int niter = K / 32;
    issue(0, 0);
    cpcommit();
    int st = 0;
    for (int it = 0; it < niter; ++it) {
        if (it + 1 < niter) {
            issue(st ^ 1, (it + 1) * 32);
            cpcommit();
            cpwait<1>();
        } else {
            cpwait<0>();
        }
        __syncthreads();
        const fp16* base = sm + st * 2 * FMATB;
#pragma unroll
        for (int ks = 0; ks < 32; ks += 16) {
            uint32_t ah[4][4], bh[2][4];
#pragma unroll
            for (int mi = 0; mi < 4; mi++)
                ldsm4(ah[mi], su(base + (wm * 64 + mi * 16 + lrow) * SST + ks + lcol));
#pragma unroll
            for (int p = 0; p < 2; p++)
                ldsm4(bh[p], su(base + FMATB + (wn * 32 + p * 16 + lrow) * SST + ks + lcol));
#pragma unroll
            for (int mi = 0; mi < 4; mi++)
#pragma unroll
                for (int ni = 0; ni < 4; ni++) {
                    const int p = ni >> 1, q = ni & 1;
                    mmah(acc[mi][ni], ah[mi], bh[p][q], bh[p][q + 2]);
                }
        }
        __syncthreads();
        st ^= 1;
    }

#pragma unroll
    for (int mi = 0; mi < 4; mi++)
#pragma unroll
        for (int ni = 0; ni < 4; ni++) {
            int gn0 = bn + wn * 32 + ni * 8 + tg * 2;
#pragma unroll
            for (int half = 0; half < 2; half++) {
                int gm = bm + wm * 64 + mi * 16 + g + half * 8;
                if (gm >= Meff) continue;
                int orow = useRmap ? g_rmap[gm] : gm;
#pragma unroll
                for (int q = 0; q < 2; q++) {
                    int gn = gn0 + q;
                    if (gn >= N) continue;
                    float v = acc[mi][ni][half * 2 + q];
                    if (bias) v += bias[gn];
                    C[(size_t)orow * ldc + gn] = v;
                }
            }
        }
}

// -------------------- fp32 -> fp16 converter (+ build_map in last block) --------------
struct Seg { const float4* src; uint2* dst; int srcld4; int lc4; long long start; };
struct SegArr { Seg s[10]; long long total; };

__global__ void conv_all(SegArr sa, const int* __restrict__ lengths) {
    if (blockIdx.x == gridDim.x - 1) {
        // build active-row map
        __shared__ int cnt[20], off[21];
        int tid = threadIdx.x;
        if (tid < 20) {
            int c = 0;
            for (int b = 0; b < BQ; b++) c += (lengths[b] > tid);
            cnt[tid] = c;
        }
        __syncthreads();
        if (tid == 0) {
            off[0] = 0;
            for (int t = 0; t < 20; t++) off[t + 1] = off[t] + cnt[t];
            g_mact = off[20];
        }
        __syncthreads();
        for (int t = 0; t < 20; t++)
            for (int b = tid; b < cnt[t]; b += 256)
                g_rmap[off[t] + b] = b * TT + t;
        return;
    }
    long long i = (long long)blockIdx.x * blockDim.x + threadIdx.x;
    if (i >= sa.total) return;
    int k = 0;
#pragma unroll
    for (int j = 1; j < 10; j++) if (i >= sa.s[j].start) k = j;
    Seg sg = sa.s[k];
    long long idx = i - sg.start;
    int row = (int)(idx >> sg.lc4);
    int c   = (int)(idx & ((1 << sg.lc4) - 1));
    float4 v = sg.src[(long long)row * sg.srcld4 + c];
    __half2 a = __floats2half2_rn(v.x, v.y);
    __half2 b = __floats2half2_rn(v.z, v.w);
    uint2 o;
    o.x = *reinterpret_cast<uint32_t*>(&a);
    o.y = *reinterpret_cast<uint32_t*>(&b);
    sg.dst[idx] = o;
}

// -------------------- embedding gather (compact, fp16) --------------------
__global__ void gather_emb(const int* __restrict__ cap, const float* __restrict__ emb) {
    int i = blockIdx.x * blockDim.x + threadIdx.x;
    if (i >= BQ * TT * (EE / 4)) return;
    int r = i >> 6, e4 = i & 63;
    if (r >= g_mact) return;
    int tok = cap[g_rmap[r]];
    float4 v = reinterpret_cast<const float4*>(emb)[(size_t)tok * 64 + e4];
    __half2 a = __floats2half2_rn(v.x, v.y);
    __half2 b = __floats2half2_rn(v.z, v.w);
    uint2 o;
    o.x = *reinterpret_cast<uint32_t*>(&a);
    o.y = *reinterpret_cast<uint32_t*>(&b);
    reinterpret_cast<uint2*>(g_embf)[(size_t)r * 64 + e4] = o;
}

// -------------------- fused pre-pass: vproj + gates_x + init + zfill --------------------
// grid.x = 98 + 320 + 96 + 640 = 1154
__global__ void __launch_bounds__(256, 2) multi_pre(
    const int* __restrict__ lengths, float* __restrict__ out)
{
    extern __shared__ __align__(16) char smraw[];
    const int bx = blockIdx.x;
    if (bx < 98) {
        // vproj partials: spatial @ Wv^T, split-K x2
        int y = bx % 49, kz = bx / 49;
        gemm_body(g_spf + kz * 256, DD, g_wvf + kz * 256, DD,
                  g_vpart[kz], KK_, BQ * KK_, KK_, 256, y * 128, 0,
                  nullptr, 0, smraw);
    } else if (bx < 418) {
        // gates_x = embseq_compact @ W_ih[:,:E]^T (active rows only)
        int i = bx - 98;
        int x = i & 15, y = i >> 4;
        int mact = g_mact;
        if (y * 128 >= mact) return;
        gemm_body(g_embf, EE, g_wihef, EE, g_gatesx, G4,
                  mact, G4, EE, y * 128, x * 128, nullptr, 0, smraw);
    } else if (bx < 514) {
        // init partials: global @ [Winit_h;Winit_m;W_ihD]^T, split-K x4
        int i = bx - 418;
        int x = i % 24, kz = i / 24;
        gemm_body(g_glf + kz * 128, DD, g_wcatf + kz * 128, DD,
                  g_ipart[kz], 3072, BQ, 3072, 128, 0, x * 128,
                  nullptr, 0, smraw);
    } else {
        // zero-fill inactive output rows (4 rows per CTA)
        int i = bx - 514;
        float4 z = make_float4(0.f, 0.f, 0.f, 0.f);
#pragma unroll
        for (int k = 0; k < 4; k++) {
            int row = i * 4 + k;
            int b = row / TT, t = row % TT;
            if (lengths[b] > t) continue;
            float4* o = reinterpret_cast<float4*>(out + (size_t)row * VV);
            for (int q = threadIdx.x; q < VV / 4; q += 256) o[q] = z;
        }
    }
}

// -------------------- vocab GEMM: out = s_compact @ Wp^T + bp (rmap scatter) --------
__global__ void __launch_bounds__(256, 2) gemm_vocab(
    float* __restrict__ out, const float* __restrict__ bias)
{
    int mact = g_mact;
    if ((int)blockIdx.y * 128 >= mact) return;
    extern __shared__ __align__(16) char smraw[];
    gemm_body(g_sf, DD, g_wpf, DD, out, VV, mact, VV, DD,
              blockIdx.y * 128, blockIdx.x * 128, bias, 1, smraw);
}

// -------------------- pod barrier (17 CTAs, monotonic, replay-safe) --------------------
__device__ __forceinline__ void podbar(unsigned* cnt, unsigned* gen, unsigned rr) {
    __syncthreads();
    if (threadIdx.x == 0) {
        unsigned old;
        asm volatile("atom.add.release.gpu.u32 %0,[%1],1;"
                     : "=r"(old) : "l"(cnt) : "memory");
        if (old == rr * 17u + 16u) {
            asm volatile("st.release.gpu.u32 [%0],%1;"
                         :: "l"(gen), "r"(rr + 1u) : "memory");
        }
        unsigned v;
        do {
            asm volatile("ld.acquire.gpu.u32 %0,[%1];"
                         : "=r"(v) : "l"(gen) : "memory");
        } while ((int)(v - (rr + 1u)) < 0);
    }
    __syncthreads();
}

// -------------------- pod-decomposed recurrence kernel --------------------
#define RST2 520
#define RSM2 ((128 + 16) * RST2 * 2 + 3 * 52 * 4 + 43 * 4 + 64)

__global__ __launch_bounds__(256, 1) void recur_kernel(
    const float* __restrict__ b_hh,
    const int*   __restrict__ lengths,
    const float* __restrict__ bg,
    const float* __restrict__ wh,
    const float* __restrict__ bh_att,
    const float* __restrict__ b_init_h,
    const float* __restrict__ b_init_m,
    const float* __restrict__ b_ih,
    const float* __restrict__ bv)
{
    extern __shared__ __align__(16) char dsm[];
    fp16* sB = (fp16*)dsm;                   // [128][RST2] W slice (persistent)
    fp16* sA = sB + 128 * RST2;              // [16][RST2]  pod h rows
    float* sh_gh    = (float*)(sA + 16 * RST2);
    float* sh_z     = sh_gh + 52;
    float* sh_alpha = sh_z + 52;
    int*   rs_cnt   = (int*)(sh_alpha + 52);   // [21]
    int*   rs_off   = rs_cnt + 21;             // [22]

    const int c = blockIdx.x;
    const int p = c / 17, j = c % 17;
    const int pb0 = p * 16;
    const int b = pb0 + j;                   // phase2 batch (j<16 only)
    const int tid = threadIdx.x;
    const int w = tid >> 5, lane = tid & 31;
    const int g = lane >> 2, tg = lane & 3;
    const int lrow = lane & 15, lcol = (lane >> 4) * 8;
    const int wid = w;
    const float bh0 = bh_att[0];

    unsigned* pcnt = &g_pbar[p][0];
    unsigned* pgen = &g_pgen[p][0];
    unsigned rbase;
    asm volatile("ld.acquire.gpu.u32 %0,[%1];" : "=r"(rbase) : "l"(pgen) : "memory");
    unsigned round = 0;

    // ---- rs arrays (compact offsets) ----
    if (tid < 21) {
        int cc = 0;
        for (int bb = 0; bb < BQ; bb++) cc += (lengths[bb] > tid);
        rs_cnt[tid] = cc;
    }
    __syncthreads();
    if (tid == 0) {
        rs_off[0] = 0;
        for (int u = 0; u < 21; u++) rs_off[u + 1] = rs_off[u] + rs_cnt[u];
    }
    __syncthreads();

    // ---- pod length ----
    int pod_len = 0;
#pragma unroll
    for (int q = 0; q < 16; q++) {
        int l = lengths[pb0 + q];
        pod_len = l > pod_len ? l : pod_len;
    }

    float hp[2], mr[2], gb[8];
    int len = 0;

    // ---- prologue: per-batch init reduce (j<16), d = {2*tid, 2*tid+1} ----
    if (j < 16) {
        len = lengths[b];
#pragma unroll
        for (int blk = 0; blk < 6; blk++) {
            int base = blk * 512 + 2 * tid;
            float2 v = make_float2(0.f, 0.f);
#pragma unroll
            for (int q = 0; q < 4; q++) {
                float2 ip = *(const float2*)&g_ipart[q][b * 3072 + base];
                v.x += ip.x; v.y += ip.y;
            }
            if (blk == 0) {
                float2 bi = *(const float2*)&b_init_h[base];
                hp[0] = v.x + bi.x; hp[1] = v.y + bi.y;
                ((__half2*)g_hf)[b * 256 + tid] = __floats2half2_rn(hp[0], hp[1]);
            } else if (blk == 1) {
                float2 bi = *(const float2*)&b_init_m[base - 512];
                mr[0] = v.x + bi.x; mr[1] = v.y + bi.y;
            } else {
                int col = base - 1024;
                float2 bih = *(const float2*)&b_ih[col];
                float2 bhh = *(const float2*)&b_hh[col];
                gb[(blk - 2) * 2 + 0] = v.x + bih.x + bhh.x;
                gb[(blk - 2) * 2 + 1] = v.y + bih.y + bhh.y;
            }
        }
        for (int i = tid; i < KK_ * KK_; i += 256) {
            int r = b * KK_ + i / KK_, q = i % KK_;
            g_vproj[(size_t)r * KK_ + q] =
                g_vpart[0][(size_t)r * KK_ + q] + g_vpart[1][(size_t)r * KK_ + q] + bv[q];
        }
    }
    // ---- preload W slice: rows [128j, 128j+128), K=512 ----
#pragma unroll
    for (int k = 0; k < 32; k++) {
        int cid = tid + k * 256;
        int row = cid >> 6, ch = cid & 63;
        *(float4*)(sB + row * RST2 + ch * 8) =
            *(const float4*)(g_wc2f + (size_t)(j * 128 + row) * DD + ch * 8);
    }
    podbar(pcnt, pgen, rbase + round); round++;

    for (int t = 0; t <= pod_len; t++) {
        // ---------------- phase 1: gates rows = h_pod @ Wslice^T ----------------
        {
#pragma unroll
            for (int k = 0; k < 4; k++) {
                int cid = tid + k * 256;
                int row = cid >> 6, ch = cid & 63;
                *(float4*)(sA + row * RST2 + ch * 8) =
                    *(const float4*)(g_hf + (size_t)(pb0 + row) * DD + ch * 8);
            }
            __syncthreads();

            float acc[2][4];
#pragma unroll
            for (int q = 0; q < 2; q++)
#pragma unroll
                for (int i = 0; i < 4; i++) acc[q][i] = 0.f;

#pragma unroll
            for (int ks = 0; ks < 512; ks += 16) {
                uint32_t a4[4], b4[4];
                ldsm4(a4, su(sA + lrow * RST2 + ks + lcol));
                ldsm4(b4, su(sB + (w * 16 + lrow) * RST2 + ks + lcol));
                mmah(acc[0], a4, b4[0], b4[2]);
                mmah(acc[1], a4, b4[1], b4[3]);
            }

#pragma unroll
            for (int q = 0; q < 2; q++) {
                int col = j * 128 + w * 16 + q * 8 + tg * 2;
                float* r0 = g_g2 + (size_t)(pb0 + g) * NW + col;
                float* r1 = g_g2 + (size_t)(pb0 + g + 8) * NW + col;
                r0[0] = acc[q][0]; r0[1] = acc[q][1];
                r1[0] = acc[q][2]; r1[1] = acc[q][3];
            }
        }
        podbar(pcnt, pgen, rbase + round); round++;
        // ---------------- phase 2 (j < 16), d = {2*tid, 2*tid+1} ----------------
        if (j < 16) {
            const float* grow = g_g2 + (size_t)b * NW;
            // ---- attention for step t-1 ----
            if (t >= 1 && len > t - 1) {
                if (tid < KK_) sh_gh[tid] = bg[tid] + grow[2048 + tid];
                __syncthreads();
                for (int k = wid; k < KK_; k += 8) {
                    const float* vp = g_vproj + (size_t)(b * KK_ + k) * KK_;
                    float s = 0.f;
                    for (int q = lane; q < KK_; q += 32) s += ftanh(vp[q] + sh_gh[q]) * wh[q];
#pragma unroll
                    for (int o = 16; o; o >>= 1) s += __shfl_xor_sync(0xffffffffu, s, o);
                    if (lane == 0) sh_z[k] = s + bh0;
                }
                __syncthreads();
                if (wid == 0) {
                    float mx = -3.0e38f;
                    for (int k = lane; k < KK_; k += 32) mx = fmaxf(mx, sh_z[k]);
#pragma unroll
                    for (int o = 16; o; o >>= 1) mx = fmaxf(mx, __shfl_xor_sync(0xffffffffu, mx, o));
                    float sm = 0.f;
                    for (int k = lane; k < KK_; k += 32) { float e = __expf(sh_z[k] - mx); sh_alpha[k] = e; sm += e; }
#pragma unroll
                    for (int o = 16; o; o >>= 1) sm += __shfl_xor_sync(0xffffffffu, sm, o);
                    float inv = 1.f / sm;
                    for (int k = lane; k < KK_; k += 32) sh_alpha[k] *= inv;
                }
                __syncthreads();
                const __half2* sp2 = (const __half2*)(g_spf + (size_t)b * KK_ * DD);
                float ccx = 0.f, ccy = 0.f;
#pragma unroll
                for (int k = 0; k < KK_; k++) {
                    float al = sh_alpha[k];
                    float2 f = __half22float2(sp2[k * 256 + tid]);
                    ccx = fmaf(al, f.x, ccx);
                    ccy = fmaf(al, f.y, ccy);
                }
                const int spos = rs_off[t - 1] + b;
                ((__half2*)g_sf)[(size_t)spos * 256 + tid] =
                    __floats2half2_rn(ccx + hp[0], ccy + hp[1]);
            }
            // ---- LSTM for step t ----
            if (t < TT && len > t) {
                const float2* gx2 = (const float2*)(g_gatesx + (size_t)(rs_off[t] + b) * G4);
                const float2* gr2 = (const float2*)grow;
                float2 vi = gx2[0 * 256 + tid], ri = gr2[0 * 256 + tid];
                float2 vf = gx2[1 * 256 + tid], rf = gr2[1 * 256 + tid];
                float2 vg = gx2[2 * 256 + tid], rg = gr2[2 * 256 + tid];
                float2 vo = gx2[3 * 256 + tid], ro = gr2[3 * 256 + tid];
                float gix = vi.x + ri.x + gb[0], giy = vi.y + ri.y + gb[1];
                float gfx = vf.x + rf.x + gb[2], gfy = vf.y + rf.y + gb[3];
                float ggx = vg.x + rg.x + gb[4], ggy = vg.y + rg.y + gb[5];
                float gox = vo.x + ro.x + gb[6], goy = vo.y + ro.y + gb[7];
                float mnx = fsig(gfx) * mr[0] + fsig(gix) * ftanh(ggx);
                float mny = fsig(gfy) * mr[1] + fsig(giy) * ftanh(ggy);
                float hvx = fsig(gox) * ftanh(mnx);
                float hvy = fsig(goy) * ftanh(mny);
                mr[0] = mnx; mr[1] = mny;
                hp[0] = hvx; hp[1] = hvy;
                ((__half2*)g_hf)[b * 256 + tid] = __floats2half2_rn(hvx, hvy);
            }
        }
        if (t < pod_len) { podbar(pcnt, pgen, rbase + round); round++; }
    }
}

// -------------------- launch --------------------
extern "C" void kernel_launch(void* const* d_in, const int* in_sizes, int n_in,
                              void* d_out, int out_size)
{
    const float* spatial      = (const float*)d_in[0];
    const float* global_feats = (const float*)d_in[1];
    const int*   captions     = (const int*)d_in[2];
    const int*   lengths      = (const int*)d_in[3];
    const float* emb          = (const float*)d_in[4];
    const float* W_init_h     = (const float*)d_in[5];
    const float* b_init_h     = (const float*)d_in[6];
    const float* W_init_m     = (const float*)d_in[7];
    const float* b_init_m     = (const float*)d_in[8];
    const float* W_ih         = (const float*)d_in[9];
    const float* b_ih         = (const float*)d_in[10];
    const float* W_hh         = (const float*)d_in[11];
    const float* b_hh         = (const float*)d_in[12];
    const float* Wv           = (const float*)d_in[13];
    const float* bv           = (const float*)d_in[14];
    const float* Wg           = (const float*)d_in[15];
    const float* bg           = (const float*)d_in[16];
    const float* wh           = (const float*)d_in[17];
    const float* bh_att       = (const float*)d_in[18];
    const float* Wp           = (const float*)d_in[19];
    const float* bp           = (const float*)d_in[20];
    float* out = (float*)d_out;

#define GETP(var, sym) void* var; cudaGetSymbolAddress(&var, sym)
    GETP(p_glf, g_glf);      GETP(p_wihef, g_wihef);
    GETP(p_wcatf, g_wcatf);  GETP(p_wc2f, g_wc2f);
    GETP(p_wvf, g_wvf);      GETP(p_wpf, g_wpf);
    GETP(p_spf, g_spf);
#undef GETP

    const int FSM = 2 * 2 * FMATB * 2;                       // 40960 B
    cudaFuncSetAttribute(multi_pre, cudaFuncAttributeMaxDynamicSharedMemorySize, FSM);
    cudaFuncSetAttribute(gemm_vocab, cudaFuncAttributeMaxDynamicSharedMemorySize, FSM);
    cudaFuncSetAttribute(recur_kernel, cudaFuncAttributeMaxDynamicSharedMemorySize, RSM2);

    // ---- 1. convert fp32 -> fp16 (+ build active-row map in last block) ----
    SegArr sa;
    long long pos = 0;
    auto seg = [&](int i, const float* src, void* dst, int srcld, int cols, int rows) {
        sa.s[i].src = (const float4*)src;
        sa.s[i].dst = (uint2*)dst;
        sa.s[i].srcld4 = srcld / 4;
        sa.s[i].lc4 = (cols / 4 == 64) ? 6 : 7;
        sa.s[i].start = pos;
        pos += (long long)rows * (cols / 4);
    };
    seg(0, global_feats, p_glf, DD, DD, BQ);
    seg(1, W_init_h, p_wcatf, DD, DD, DD);
    seg(2, W_init_m, (fp16*)p_wcatf + 512 * DD, DD, DD, DD);
    seg(3, W_ih, p_wihef, EE + DD, EE, G4);
    seg(4, W_ih + EE, (fp16*)p_wcatf + 1024 * DD, EE + DD, DD, G4);
    seg(5, W_hh, p_wc2f, DD, DD, G4);
    seg(6, Wg, (fp16*)p_wc2f + 2048 * DD, DD, DD, KK_);
    seg(7, Wv, p_wvf, DD, DD, KK_);
    seg(8, Wp, p_wpf, DD, DD, VV);
    seg(9, spatial, p_spf, DD, DD, BQ * KK_);
    sa.total = pos;
    conv_all<<<(unsigned)((pos + 255) / 256) + 1, 256>>>(sa, lengths);

    // ---- 2. gather caption embeddings (compact, fp16) ----
    gather_emb<<<(BQ * TT * (EE / 4) + 255) / 256, 256>>>(captions, emb);

    // ---- 3. fused pre-pass: vproj + gates_x + init + zfill (concurrent) ----
    multi_pre<<<1154, 256, FSM>>>(lengths, out);

    // ---- 4. recurrence (pod-decomposed) ----
    recur_kernel<<<136, 256, RSM2>>>(b_hh, lengths, bg, wh, bh_att,
                                     b_init_h, b_init_m, b_ih, bv);

    // ---- 5. logits = s_compact @ Wp^T + bp, scattered via rmap ----
    gemm_vocab<<<dim3(79, 20), 256, FSM>>>(out, bp);
}

// round 15
// speedup vs baseline: 1.7233x; 1.1515x over previous
#include <cuda_runtime.h>
#include <cuda_fp16.h>
#include <math.h>
#include <stdint.h>

#define BQ  128
#define KK_ 49
#define DD  512
#define EE  256
#define VV  10000
#define TT  20
#define G4  2048
#define NW  2176          // padded gates+Wg width: 2048 + 49 -> 17*128
#define PODS 8
typedef __half fp16;

// -------------------- device scratch (static) --------------------
__device__ __align__(128) fp16 g_embf[BQ*TT*EE];
__device__ __align__(128) fp16 g_glf[BQ*DD];
__device__ __align__(128) fp16 g_wihef[G4*EE];
__device__ __align__(128) fp16 g_wcatf[3072*DD];   // [Winit_h;Winit_m;W_ih_D]
__device__ __align__(128) fp16 g_wc2f[NW*DD];      // [W_hh;Wg;0pad]
__device__ __align__(128) fp16 g_wvf[KK_*DD];
__device__ __align__(128) fp16 g_wpf[VV*DD];
__device__ __align__(128) fp16 g_spf[BQ*KK_*DD];
__device__ __align__(128) fp16 g_hf[BQ*DD];
__device__ __align__(128) fp16 g_sf[BQ*TT*DD];     // compacted active rows (s)
__device__ __align__(128) fp16 g_hh[BQ*TT*DD];     // compacted h history
__device__ __align__(128) float g_alpha[BQ*TT*52]; // compacted attention weights
__device__ __align__(128) float g_gatesx[BQ*TT*G4];// compacted active rows
__device__ __align__(128) float g_g2[BQ*NW];       // gates+gh rows
__device__ __align__(128) float g_ipart[4][BQ*3072];
__device__ __align__(128) float g_vpart[2][BQ*KK_*KK_];
__device__ int g_rmap[BQ*TT];     // compact row -> b*TT+t
__device__ int g_mact;            // number of active rows
__device__ unsigned g_pbar[PODS][32];   // pod barrier counters (monotonic)
__device__ unsigned g_pgen[PODS][32];   // pod generations (monotonic)

// -------------------- helpers --------------------
__device__ __forceinline__ uint32_t su(const void* p) {
    return (uint32_t)__cvta_generic_to_shared(p);
}
__device__ __forceinline__ void cpa16(uint32_t sa, const void* ga, uint32_t sz) {
    asm volatile("cp.async.cg.shared.global [%0],[%1],16,%2;\n" :: "r"(sa), "l"(ga), "r"(sz));
}
__device__ __forceinline__ void cpcommit() { asm volatile("cp.async.commit_group;\n"); }
template<int N> __device__ __forceinline__ void cpwait() {
    asm volatile("cp.async.wait_group %0;\n" :: "n"(N));
}
__device__ __forceinline__ void ldsm4(uint32_t* r, uint32_t a) {
    asm volatile("ldmatrix.sync.aligned.m8n8.x4.shared.b16 {%0,%1,%2,%3},[%4];\n"
                 : "=r"(r[0]), "=r"(r[1]), "=r"(r[2]), "=r"(r[3]) : "r"(a));
}
__device__ __forceinline__ void mmah(float* c, const uint32_t* a, uint32_t b0, uint32_t b1) {
    asm volatile(
        "mma.sync.aligned.m16n8k16.row.col.f32.f16.f16.f32 "
        "{%0,%1,%2,%3},{%4,%5,%6,%7},{%8,%9},{%0,%1,%2,%3};\n"
        : "+f"(c[0]), "+f"(c[1]), "+f"(c[2]), "+f"(c[3])
        : "r"(a[0]), "r"(a[1]), "r"(a[2]), "r"(a[3]), "r"(b0), "r"(b1));
}
__device__ __forceinline__ float fsig(float x) { return 1.f / (1.f + __expf(-x)); }
__device__ __forceinline__ float ftanh(float x) {
    float e = __expf(2.f * x);
    return 1.f - 2.f / (e + 1.f);
}

// -------------------- shared fp16 GEMM body (128x128 tile, 2-stage) --------------------
#define SST   40
#define FMATB (128 * SST)

__device__ __forceinline__ void gemm_body(
    const fp16* __restrict__ A, int lda,
    const fp16* __restrict__ B, int ldb,
    float* __restrict__ C, int ldc,
    int Meff, int N, int K, int bm, int bn,
    const float* __restrict__ bias, int useRmap, char* smraw)
{
    fp16* sm = (fp16*)smraw;                     // [2][2][FMATB]
    const int tid = threadIdx.x;
    const int w = tid >> 5, lane = tid & 31;
    const int wm = w >> 2, wn = w & 3;
    const int g = lane >> 2, tg = lane & 3;
    const int lrow = lane & 15, lcol = (lane >> 4) * 8;
    const int ldrow = tid >> 1, ldch = (tid & 1) * 2;

    const fp16* aSrc = A + (size_t)(bm + ldrow) * lda + ldch * 8;
    int gn_l = bn + ldrow;
    uint32_t szb = (gn_l < N) ? 16u : 0u;
    if (gn_l >= N) gn_l = 0;
    const fp16* bSrc = B + (size_t)gn_l * ldb + ldch * 8;
    const uint32_t da = su(sm + ldrow * SST + ldch * 8);
    const uint32_t db = da + FMATB * 2;

    float acc[4][4][4];
#pragma unroll
    for (int i = 0; i < 4; i++)
#pragma unroll
        for (int j = 0; j < 4; j++)
#pragma unroll
            for (int q = 0; q < 4; q++) acc[i][j][q] = 0.f;

    auto issue = [&](int stg, int k0) {
        uint32_t so = (uint32_t)(stg * 2 * FMATB) * 2;
        cpa16(da + so,      aSrc + k0,     16);
        cpa16(da + so + 16, aSrc + k0 + 8, 16);
        cpa16(db + so,      bSrc + k0,     szb);
        cpa16(db + so + 16, bSrc + k0 + 8, szb);
    };

    const int niter = K / 32;
    issue(0, 0);
    cpcommit();
    int st = 0;
    for (int it = 0; it < niter; ++it) {
        if (it + 1 < niter) {
            issue(st ^ 1, (it + 1) * 32);
            cpcommit();
            cpwait<1>();
        } else {
            cpwait<0>();
        }
        __syncthreads();
        const fp16* base = sm + st * 2 * FMATB;
#pragma unroll
        for (int ks = 0; ks < 32; ks += 16) {
            uint32_t ah[4][4], bh[2][4];
#pragma unroll
            for (int mi = 0; mi < 4; mi++)
                ldsm4(ah[mi], su(base + (wm * 64 + mi * 16 + lrow) * SST + ks + lcol));
#pragma unroll
            for (int p = 0; p < 2; p++)
                ldsm4(bh[p], su(base + FMATB + (wn * 32 + p * 16 + lrow) * SST + ks + lcol));
#pragma unroll
            for (int mi = 0; mi < 4; mi++)
#pragma unroll
                for (int ni = 0; ni < 4; ni++) {
                    const int p = ni >> 1, q = ni & 1;
                    mmah(acc[mi][ni], ah[mi], bh[p][q], bh[p][q + 2]);
                }
        }
        __syncthreads();
        st ^= 1;
    }

#pragma unroll
    for (int mi = 0; mi < 4; mi++)
#pragma unroll
        for (int ni = 0; ni < 4; ni++) {
            int gn0 = bn + wn * 32 + ni * 8 + tg * 2;
#pragma unroll
            for (int half = 0; half < 2; half++) {
                int gm = bm + wm * 64 + mi * 16 + g + half * 8;
                if (gm >= Meff) continue;
                int orow = useRmap ? g_rmap[gm] : gm;
#pragma unroll
                for (int q = 0; q < 2; q++) {
                    int gn = gn0 + q;
                    if (gn >= N) continue;
                    float v = acc[mi][ni][half * 2 + q];
                    if (bias) v += bias[gn];
                    C[(size_t)orow * ldc + gn] = v;
                }
            }
        }
}

// -------------------- fp32 -> fp16 converter (+ build_map in last block) --------------
struct Seg { const float4* src; uint2* dst; int srcld4; int lc4; long long start; };
struct SegArr { Seg s[10]; long long total; };

__global__ void conv_all(SegArr sa, const int* __restrict__ lengths) {
    if (blockIdx.x == gridDim.x - 1) {
        __shared__ int cnt[20], off[21];
        int tid = threadIdx.x;
        if (tid < 20) {
            int c = 0;
            for (int b = 0; b < BQ; b++) c += (lengths[b] > tid);
            cnt[tid] = c;
        }
        __syncthreads();
        if (tid == 0) {
            off[0] = 0;
            for (int t = 0; t < 20; t++) off[t + 1] = off[t] + cnt[t];
            g_mact = off[20];
        }
        __syncthreads();
        for (int t = 0; t < 20; t++)
            for (int b = tid; b < cnt[t]; b += 256)
                g_rmap[off[t] + b] = b * TT + t;
        return;
    }
    long long i = (long long)blockIdx.x * blockDim.x + threadIdx.x;
    if (i >= sa.total) return;
    int k = 0;
#pragma unroll
    for (int j = 1; j < 10; j++) if (i >= sa.s[j].start) k = j;
    Seg sg = sa.s[k];
    long long idx = i - sg.start;
    int row = (int)(idx >> sg.lc4);
    int c   = (int)(idx & ((1 << sg.lc4) - 1));
    float4 v = sg.src[(long long)row * sg.srcld4 + c];
    __half2 a = __floats2half2_rn(v.x, v.y);
    __half2 b = __floats2half2_rn(v.z, v.w);
    uint2 o;
    o.x = *reinterpret_cast<uint32_t*>(&a);
    o.y = *reinterpret_cast<uint32_t*>(&b);
    sg.dst[idx] = o;
}

// -------------------- embedding gather (compact, fp16) --------------------
__global__ void gather_emb(const int* __restrict__ cap, const float* __restrict__ emb) {
    int i = blockIdx.x * blockDim.x + threadIdx.x;
    if (i >= BQ * TT * (EE / 4)) return;
    int r = i >> 6, e4 = i & 63;
    if (r >= g_mact) return;
    int tok = cap[g_rmap[r]];
    float4 v = reinterpret_cast<const float4*>(emb)[(size_t)tok * 64 + e4];
    __half2 a = __floats2half2_rn(v.x, v.y);
    __half2 b = __floats2half2_rn(v.z, v.w);
    uint2 o;
    o.x = *reinterpret_cast<uint32_t*>(&a);
    o.y = *reinterpret_cast<uint32_t*>(&b);
    reinterpret_cast<uint2*>(g_embf)[(size_t)r * 64 + e4] = o;
}

// -------------------- fused pre-pass: vproj + gates_x + init + zfill --------------------
__global__ void __launch_bounds__(256, 2) multi_pre(
    const int* __restrict__ lengths, float* __restrict__ out)
{
    extern __shared__ __align__(16) char smraw[];
    const int bx = blockIdx.x;
    if (bx < 98) {
        int y = bx % 49, kz = bx / 49;
        gemm_body(g_spf + kz * 256, DD, g_wvf + kz * 256, DD,
                  g_vpart[kz], KK_, BQ * KK_, KK_, 256, y * 128, 0,
                  nullptr, 0, smraw);
    } else if (bx < 418) {
        int i = bx - 98;
        int x = i & 15, y = i >> 4;
        int mact = g_mact;
        if (y * 128 >= mact) return;
        gemm_body(g_embf, EE, g_wihef, EE, g_gatesx, G4,
                  mact, G4, EE, y * 128, x * 128, nullptr, 0, smraw);
    } else if (bx < 514) {
        int i = bx - 418;
        int x = i % 24, kz = i / 24;
        gemm_body(g_glf + kz * 128, DD, g_wcatf + kz * 128, DD,
                  g_ipart[kz], 3072, BQ, 3072, 128, 0, x * 128,
                  nullptr, 0, smraw);
    } else {
        int i = bx - 514;
        float4 z = make_float4(0.f, 0.f, 0.f, 0.f);
#pragma unroll
        for (int k = 0; k < 4; k++) {
            int row = i * 4 + k;
            int b = row / TT, t = row % TT;
            if (lengths[b] > t) continue;
            float4* o = reinterpret_cast<float4*>(out + (size_t)row * VV);
            for (int q = threadIdx.x; q < VV / 4; q += 256) o[q] = z;
        }
    }
}

// -------------------- context kernel: s = alpha @ spatial + h_hist --------------------
__global__ void __launch_bounds__(256, 4) ctx_kernel()
{
    int r = blockIdx.x;
    if (r >= g_mact) return;
    __shared__ float sal[52];
    int tid = threadIdx.x;
    if (tid < KK_) sal[tid] = g_alpha[(size_t)r * 52 + tid];
    __syncthreads();
    int b = g_rmap[r] / TT;
    const __half2* sp2 = (const __half2*)(g_spf + (size_t)b * KK_ * DD);
    float ccx = 0.f, ccy = 0.f;
#pragma unroll
    for (int k = 0; k < KK_; k++) {
        float al = sal[k];
        float2 f = __half22float2(sp2[k * 256 + tid]);
        ccx = fmaf(al, f.x, ccx);
        ccy = fmaf(al, f.y, ccy);
    }
    float2 h = __half22float2(((const __half2*)g_hh)[(size_t)r * 256 + tid]);
    ((__half2*)g_sf)[(size_t)r * 256 + tid] = __floats2half2_rn(ccx + h.x, ccy + h.y);
}

// -------------------- vocab GEMM --------------------
__global__ void __launch_bounds__(256, 2) gemm_vocab(
    float* __restrict__ out, const float* __restrict__ bias)
{
    int mact = g_mact;
    if ((int)blockIdx.y * 128 >= mact) return;
    extern __shared__ __align__(16) char smraw[];
    gemm_body(g_sf, DD, g_wpf, DD, out, VV, mact, VV, DD,
              blockIdx.y * 128, blockIdx.x * 128, bias, 1, smraw);
}

// -------------------- pod barrier (17 CTAs, monotonic, replay-safe) --------------------
__device__ __forceinline__ void podbar(unsigned* cnt, unsigned* gen, unsigned rr) {
    __syncthreads();
    if (threadIdx.x == 0) {
        unsigned old;
        asm volatile("atom.add.release.gpu.u32 %0,[%1],1;"
                     : "=r"(old) : "l"(cnt) : "memory");
        if (old == rr * 17u + 16u) {
            asm volatile("st.release.gpu.u32 [%0],%1;"
                         :: "l"(gen), "r"(rr + 1u) : "memory");
        }
        unsigned v;
        do {
            asm volatile("ld.acquire.gpu.u32 %0,[%1];"
                         : "=r"(v) : "l"(gen) : "memory");
        } while ((int)(v - (rr + 1u)) < 0);
    }
    __syncthreads();
}

// -------------------- pod-decomposed recurrence (alpha-only attention) --------------
#define RST2 520
#define RSM2 ((128 + 16) * RST2 * 2 + 49 * 52 * 4 + (3 * 52 + 49 + 43) * 4 + 128)

__global__ __launch_bounds__(256, 1) void recur_kernel(
    const float* __restrict__ b_hh,
    const int*   __restrict__ lengths,
    const float* __restrict__ bg,
    const float* __restrict__ wh,
    const float* __restrict__ bh_att,
    const float* __restrict__ b_init_h,
    const float* __restrict__ b_init_m,
    const float* __restrict__ b_ih,
    const float* __restrict__ bv)
{
    extern __shared__ __align__(16) char dsm[];
    fp16* sB = (fp16*)dsm;                   // [128][RST2] W slice (persistent)
    fp16* sA = sB + 128 * RST2;              // [16][RST2]  pod h rows
    float* sVP      = (float*)(sA + 16 * RST2);   // [49][52] vproj (j<16)
    float* sh_gh    = sVP + 49 * 52;
    float* sh_z     = sh_gh + 52;
    float* sh_alpha = sh_z + 52;
    float* sWH      = sh_alpha + 52;              // [49] wh
    int*   rs_cnt   = (int*)(sWH + 49);           // [21]
    int*   rs_off   = rs_cnt + 21;                // [22]

    const int c = blockIdx.x;
    const int p = c / 17, j = c % 17;
    const int pb0 = p * 16;
    const int b = pb0 + j;                   // phase2 batch (j<16 only)
    const int tid = threadIdx.x;
    const int w = tid >> 5, lane = tid & 31;
    const int g = lane >> 2, tg = lane & 3;
    const int lrow = lane & 15, lcol = (lane >> 4) * 8;
    const int wid = w;
    const float bh0 = bh_att[0];

    unsigned* pcnt = &g_pbar[p][0];
    unsigned* pgen = &g_pgen[p][0];
    unsigned rbase;
    asm volatile("ld.acquire.gpu.u32 %0,[%1];" : "=r"(rbase) : "l"(pgen) : "memory");
    unsigned round = 0;

    // ---- rs arrays + wh cache ----
    if (tid < 21) {
        int cc = 0;
        for (int bb = 0; bb < BQ; bb++) cc += (lengths[bb] > tid);
        rs_cnt[tid] = cc;
    }
    if (tid >= 32 && tid < 32 + KK_) sWH[tid - 32] = wh[tid - 32];
    __syncthreads();
    if (tid == 0) {
        rs_off[0] = 0;
        for (int u = 0; u < 21; u++) rs_off[u + 1] = rs_off[u] + rs_cnt[u];
    }
    __syncthreads();

    int pod_len = 0;
#pragma unroll
    for (int q = 0; q < 16; q++) {
        int l = lengths[pb0 + q];
        pod_len = l > pod_len ? l : pod_len;
    }

    float hp[2], mr[2], gb[8];
    int len = 0;

    // ---- prologue: per-batch init reduce + vproj->smem (j<16) ----
    if (j < 16) {
        len = lengths[b];
#pragma unroll
        for (int blk = 0; blk < 6; blk++) {
            int base = blk * 512 + 2 * tid;
            float2 v = make_float2(0.f, 0.f);
#pragma unroll
            for (int q = 0; q < 4; q++) {
                float2 ip = *(const float2*)&g_ipart[q][b * 3072 + base];
                v.x += ip.x; v.y += ip.y;
            }
            if (blk == 0) {
                float2 bi = *(const float2*)&b_init_h[base];
                hp[0] = v.x + bi.x; hp[1] = v.y + bi.y;
                ((__half2*)g_hf)[b * 256 + tid] = __floats2half2_rn(hp[0], hp[1]);
            } else if (blk == 1) {
                float2 bi = *(const float2*)&b_init_m[base - 512];
                mr[0] = v.x + bi.x; mr[1] = v.y + bi.y;
            } else {
                int col = base - 1024;
                float2 bih = *(const float2*)&b_ih[col];
                float2 bhh = *(const float2*)&b_hh[col];
                gb[(blk - 2) * 2 + 0] = v.x + bih.x + bhh.x;
                gb[(blk - 2) * 2 + 1] = v.y + bih.y + bhh.y;
            }
        }
        for (int i = tid; i < KK_ * KK_; i += 256) {
            int kk = i / KK_, q = i % KK_;
            sVP[kk * 52 + q] =
                g_vpart[0][(size_t)(b * KK_ + kk) * KK_ + q] +
                g_vpart[1][(size_t)(b * KK_ + kk) * KK_ + q] + bv[q];
        }
    }
    // ---- preload W slice: rows [128j, 128j+128), K=512 ----
#pragma unroll
    for (int k = 0; k < 32; k++) {
        int cid = tid + k * 256;
        int row = cid >> 6, ch = cid & 63;
        *(float4*)(sB + row * RST2 + ch * 8) =
            *(const float4*)(g_wc2f + (size_t)(j * 128 + row) * DD + ch * 8);
    }
    podbar(pcnt, pgen, rbase + round); round++;

    for (int t = 0; t <= pod_len; t++) {
        // ---------------- phase 1: gates rows = h_pod @ Wslice^T ----------------
        {
#pragma unroll
            for (int k = 0; k < 4; k++) {
                int cid = tid + k * 256;
                int row = cid >> 6, ch = cid & 63;
                *(float4*)(sA + row * RST2 + ch * 8) =
                    *(const float4*)(g_hf + (size_t)(pb0 + row) * DD + ch * 8);
            }
            __syncthreads();

            float acc[2][4];
#pragma unroll
            for (int q = 0; q < 2; q++)
#pragma unroll
                for (int i = 0; i < 4; i++) acc[q][i] = 0.f;

#pragma unroll
            for (int ks = 0; ks < 512; ks += 16) {
                uint32_t a4[4], b4[4];
                ldsm4(a4, su(sA + lrow * RST2 + ks + lcol));
                ldsm4(b4, su(sB + (w * 16 + lrow) * RST2 + ks + lcol));
                mmah(acc[0], a4, b4[0], b4[2]);
                mmah(acc[1], a4, b4[1], b4[3]);
            }

#pragma unroll
            for (int q = 0; q < 2; q++) {
                int col = j * 128 + w * 16 + q * 8 + tg * 2;
                float* r0 = g_g2 + (size_t)(pb0 + g) * NW + col;
                float* r1 = g_g2 + (size_t)(pb0 + g + 8) * NW + col;
                r0[0] = acc[q][0]; r0[1] = acc[q][1];
                r1[0] = acc[q][2]; r1[1] = acc[q][3];
            }
        }
        podbar(pcnt, pgen, rbase + round); round++;
        // ---------------- phase 2 (j < 16) ----------------
        if (j < 16) {
            const float* grow = g_g2 + (size_t)b * NW;
            // ---- attention z/softmax for step t-1; alpha stored ----
            if (t >= 1 && len > t - 1) {
                if (tid < KK_) sh_gh[tid] = bg[tid] + grow[2048 + tid];
                __syncthreads();
                for (int k = wid; k < KK_; k += 8) {
                    const float* vp = sVP + k * 52;
                    float s = 0.f;
                    for (int q = lane; q < KK_; q += 32) s += ftanh(vp[q] + sh_gh[q]) * sWH[q];
#pragma unroll
                    for (int o = 16; o; o >>= 1) s += __shfl_xor_sync(0xffffffffu, s, o);
                    if (lane == 0) sh_z[k] = s + bh0;
                }
                __syncthreads();
                if (wid == 0) {
                    float mx = -3.0e38f;
                    for (int k = lane; k < KK_; k += 32) mx = fmaxf(mx, sh_z[k]);
#pragma unroll
                    for (int o = 16; o; o >>= 1) mx = fmaxf(mx, __shfl_xor_sync(0xffffffffu, mx, o));
                    float sm = 0.f;
                    for (int k = lane; k < KK_; k += 32) { float e = __expf(sh_z[k] - mx); sh_alpha[k] = e; sm += e; }
#pragma unroll
                    for (int o = 16; o; o >>= 1) sm += __shfl_xor_sync(0xffffffffu, sm, o);
                    float inv = 1.f / sm;
                    for (int k = lane; k < KK_; k += 32) sh_alpha[k] *= inv;
                }
                __syncthreads();
                if (tid < KK_)
                    g_alpha[(size_t)(rs_off[t - 1] + b) * 52 + tid] = sh_alpha[tid];
            }
            // ---- LSTM for step t; h stored to g_hf + history ----
            if (t < TT && len > t) {
                const float2* gx2 = (const float2*)(g_gatesx + (size_t)(rs_off[t] + b) * G4);
                const float2* gr2 = (const float2*)grow;
                float2 vi = gx2[0 * 256 + tid], ri = gr2[0 * 256 + tid];
                float2 vf = gx2[1 * 256 + tid], rf = gr2[1 * 256 + tid];
                float2 vg = gx2[2 * 256 + tid], rg = gr2[2 * 256 + tid];
                float2 vo = gx2[3 * 256 + tid], ro = gr2[3 * 256 + tid];
                float gix = vi.x + ri.x + gb[0], giy = vi.y + ri.y + gb[1];
                float gfx = vf.x + rf.x + gb[2], gfy = vf.y + rf.y + gb[3];
                float ggx = vg.x + rg.x + gb[4], ggy = vg.y + rg.y + gb[5];
                float gox = vo.x + ro.x + gb[6], goy = vo.y + ro.y + gb[7];
                float mnx = fsig(gfx) * mr[0] + fsig(gix) * ftanh(ggx);
                float mny = fsig(gfy) * mr[1] + fsig(giy) * ftanh(ggy);
                float hvx = fsig(gox) * ftanh(mnx);
                float hvy = fsig(goy) * ftanh(mny);
                mr[0] = mnx; mr[1] = mny;
                hp[0] = hvx; hp[1] = hvy;
                __half2 hh2 = __floats2half2_rn(hvx, hvy);
                ((__half2*)g_hf)[b * 256 + tid] = hh2;
                ((__half2*)g_hh)[(size_t)(rs_off[t] + b) * 256 + tid] = hh2;
            }
        }
        if (t < pod_len) { podbar(pcnt, pgen, rbase + round); round++; }
    }
}

// -------------------- launch --------------------
extern "C" void kernel_launch(void* const* d_in, const int* in_sizes, int n_in,
                              void* d_out, int out_size)
{
    const float* spatial      = (const float*)d_in[0];
    const float* global_feats = (const float*)d_in[1];
    const int*   captions     = (const int*)d_in[2];
    const int*   lengths      = (const int*)d_in[3];
    const float* emb          = (const float*)d_in[4];
    const float* W_init_h     = (const float*)d_in[5];
    const float* b_init_h     = (const float*)d_in[6];
    const float* W_init_m     = (const float*)d_in[7];
    const float* b_init_m     = (const float*)d_in[8];
    const float* W_ih         = (const float*)d_in[9];
    const float* b_ih         = (const float*)d_in[10];
    const float* W_hh         = (const float*)d_in[11];
    const float* b_hh         = (const float*)d_in[12];
    const float* Wv           = (const float*)d_in[13];
    const float* bv           = (const float*)d_in[14];
    const float* Wg           = (const float*)d_in[15];
    const float* bg           = (const float*)d_in[16];
    const float* wh           = (const float*)d_in[17];
    const float* bh_att       = (const float*)d_in[18];
    const float* Wp           = (const float*)d_in[19];
    const float* bp           = (const float*)d_in[20];
    float* out = (float*)d_out;

#define GETP(var, sym) void* var; cudaGetSymbolAddress(&var, sym)
    GETP(p_glf, g_glf);      GETP(p_wihef, g_wihef);
    GETP(p_wcatf, g_wcatf);  GETP(p_wc2f, g_wc2f);
    GETP(p_wvf, g_wvf);      GETP(p_wpf, g_wpf);
    GETP(p_spf, g_spf);
#undef GETP

    const int FSM = 2 * 2 * FMATB * 2;                       // 40960 B
    cudaFuncSetAttribute(multi_pre, cudaFuncAttributeMaxDynamicSharedMemorySize, FSM);
    cudaFuncSetAttribute(gemm_vocab, cudaFuncAttributeMaxDynamicSharedMemorySize, FSM);
    cudaFuncSetAttribute(recur_kernel, cudaFuncAttributeMaxDynamicSharedMemorySize, RSM2);

    // ---- 1. convert fp32 -> fp16 (+ build active-row map) ----
    SegArr sa;
    long long pos = 0;
    auto seg = [&](int i, const float* src, void* dst, int srcld, int cols, int rows) {
        sa.s[i].src = (const float4*)src;
        sa.s[i].dst = (uint2*)dst;
        sa.s[i].srcld4 = srcld / 4;
        sa.s[i].lc4 = (cols / 4 == 64) ? 6 : 7;
        sa.s[i].start = pos;
        pos += (long long)rows * (cols / 4);
    };
    seg(0, global_feats, p_glf, DD, DD, BQ);
    seg(1, W_init_h, p_wcatf, DD, DD, DD);
    seg(2, W_init_m, (fp16*)p_wcatf + 512 * DD, DD, DD, DD);
    seg(3, W_ih, p_wihef, EE + DD, EE, G4);
    seg(4, W_ih + EE, (fp16*)p_wcatf + 1024 * DD, EE + DD, DD, G4);
    seg(5, W_hh, p_wc2f, DD, DD, G4);
    seg(6, Wg, (fp16*)p_wc2f + 2048 * DD, DD, DD, KK_);
    seg(7, Wv, p_wvf, DD, DD, KK_);
    seg(8, Wp, p_wpf, DD, DD, VV);
    seg(9, spatial, p_spf, DD, DD, BQ * KK_);
    sa.total = pos;
    conv_all<<<(unsigned)((pos + 255) / 256) + 1, 256>>>(sa, lengths);

    // ---- 2. gather caption embeddings (compact, fp16) ----
    gather_emb<<<(BQ * TT * (EE / 4) + 255) / 256, 256>>>(captions, emb);

    // ---- 3. fused pre-pass: vproj + gates_x + init + zfill ----
    multi_pre<<<1154, 256, FSM>>>(lengths, out);

    // ---- 4. recurrence (alpha-only attention) ----
    recur_kernel<<<136, 256, RSM2>>>(b_hh, lengths, bg, wh, bh_att,
                                     b_init_h, b_init_m, b_ih, bv);

    // ---- 5. context: s = alpha @ spatial + h_hist ----
    ctx_kernel<<<BQ * TT, 256>>>();

    // ---- 6. logits = s_compact @ Wp^T + bp, scattered via rmap ----
    gemm_vocab<<<dim3(79, 20), 256, FSM>>>(out, bp);
}

// round 16
// speedup vs baseline: 1.8981x; 1.1014x over previous
#include <cuda_runtime.h>
#include <cuda_fp16.h>
#include <math.h>
#include <stdint.h>

#define BQ  128
#define KK_ 49
#define DD  512
#define EE  256
#define VV  10000
#define TT  20
#define G4  2048
#define NW  2176          // padded gates+Wg width: 2048 + 49 -> 17*128
#define PODS 8
typedef __half fp16;

// -------------------- device scratch (static) --------------------
__device__ __align__(128) fp16 g_embf[BQ*TT*EE];
__device__ __align__(128) fp16 g_glf[BQ*DD];
__device__ __align__(128) fp16 g_wihef[G4*EE];
__device__ __align__(128) fp16 g_wcatf[3072*DD];   // [Winit_h;Winit_m;W_ih_D]
__device__ __align__(128) fp16 g_wc2f[NW*DD];      // [W_hh;Wg;0pad]
__device__ __align__(128) fp16 g_wvf[KK_*DD];
__device__ __align__(128) fp16 g_wpf[VV*DD];
__device__ __align__(128) fp16 g_spf[BQ*KK_*DD];
__device__ __align__(128) fp16 g_hf[BQ*DD];
__device__ __align__(128) fp16 g_sf[BQ*TT*DD];     // compacted active rows (s)
__device__ __align__(128) fp16 g_hh[BQ*TT*DD];     // compacted h history
__device__ __align__(128) float g_alpha[BQ*TT*52]; // compacted attention weights
__device__ __align__(128) float g_gatesx[BQ*TT*G4];// compacted active rows
__device__ __align__(128) float g_g2[BQ*NW];       // gates+gh rows
__device__ __align__(128) float g_ipart[4][BQ*3072];
__device__ __align__(128) float g_vpart[2][BQ*KK_*KK_];
__device__ int g_rmap[BQ*TT];     // compact row -> b*TT+t
__device__ int g_mact;            // number of active rows
__device__ unsigned g_f1[PODS][17][32];  // producer flags (gate slice j done), monotonic
__device__ unsigned g_f2[PODS][17][32];  // consumer flags (batch j done + h ready)

// -------------------- helpers --------------------
__device__ __forceinline__ uint32_t su(const void* p) {
    return (uint32_t)__cvta_generic_to_shared(p);
}
__device__ __forceinline__ void cpa16(uint32_t sa, const void* ga, uint32_t sz) {
    asm volatile("cp.async.cg.shared.global [%0],[%1],16,%2;\n" :: "r"(sa), "l"(ga), "r"(sz));
}
__device__ __forceinline__ void cpcommit() { asm volatile("cp.async.commit_group;\n"); }
template<int N> __device__ __forceinline__ void cpwait() {
    asm volatile("cp.async.wait_group %0;\n" :: "n"(N));
}
__device__ __forceinline__ void ldsm4(uint32_t* r, uint32_t a) {
    asm volatile("ldmatrix.sync.aligned.m8n8.x4.shared.b16 {%0,%1,%2,%3},[%4];\n"
                 : "=r"(r[0]), "=r"(r[1]), "=r"(r[2]), "=r"(r[3]) : "r"(a));
}
__device__ __forceinline__ void mmah(float* c, const uint32_t* a, uint32_t b0, uint32_t b1) {
    asm volatile(
        "mma.sync.aligned.m16n8k16.row.col.f32.f16.f16.f32 "
        "{%0,%1,%2,%3},{%4,%5,%6,%7},{%8,%9},{%0,%1,%2,%3};\n"
        : "+f"(c[0]), "+f"(c[1]), "+f"(c[2]), "+f"(c[3])
        : "r"(a[0]), "r"(a[1]), "r"(a[2]), "r"(a[3]), "r"(b0), "r"(b1));
}
__device__ __forceinline__ float fsig(float x) { return 1.f / (1.f + __expf(-x)); }
__device__ __forceinline__ float ftanh(float x) {
    float e = __expf(2.f * x);
    return 1.f - 2.f / (e + 1.f);
}
__device__ __forceinline__ void strel(unsigned* p, unsigned v) {
    asm volatile("st.release.gpu.u32 [%0],%1;" :: "l"(p), "r"(v) : "memory");
}
__device__ __forceinline__ unsigned ldacq(const unsigned* p) {
    unsigned v;
    asm volatile("ld.acquire.gpu.u32 %0,[%1];" : "=r"(v) : "l"(p) : "memory");
    return v;
}
__device__ __forceinline__ void waitflag(const unsigned* p, unsigned tgt) {
    unsigned v = ldacq(p);
    while ((int)(v - tgt) < 0) v = ldacq(p);
}

// -------------------- shared fp16 GEMM body (128x128 tile, 2-stage) --------------------
#define SST   40
#define FMATB (128 * SST)

__device__ __forceinline__ void gemm_body(
    const fp16* __restrict__ A, int lda,
    const fp16* __restrict__ B, int ldb,
    float* __restrict__ C, int ldc,
    int Meff, int N, int K, int bm, int bn,
    const float* __restrict__ bias, int useRmap, char* smraw)
{
    fp16* sm = (fp16*)smraw;                     // [2][2][FMATB]
    const int tid = threadIdx.x;
    const int w = tid >> 5, lane = tid & 31;
    const int wm = w >> 2, wn = w & 3;
    const int g = lane >> 2, tg = lane & 3;
    const int lrow = lane & 15, lcol = (lane >> 4) * 8;
    const int ldrow = tid >> 1, ldch = (tid & 1) * 2;

    const fp16* aSrc = A + (size_t)(bm + ldrow) * lda + ldch * 8;
    int gn_l = bn + ldrow;
    uint32_t szb = (gn_l < N) ? 16u : 0u;
    if (gn_l >= N) gn_l = 0;
    const fp16* bSrc = B + (size_t)gn_l * ldb + ldch * 8;
    const uint32_t da = su(sm + ldrow * SST + ldch * 8);
    const uint32_t db = da + FMATB * 2;

    float acc[4][4][4];
#pragma unroll
    for (int i = 0; i < 4; i++)
#pragma unroll
        for (int j = 0; j < 4; j++)
#pragma unroll
            for (int q = 0; q < 4; q++) acc[i][j][q] = 0.f;

    auto issue = [&](int stg, int k0) {
        uint32_t so = (uint32_t)(stg * 2 * FMATB) * 2;
        cpa16(da + so,      aSrc + k0,     16);
        cpa16(da + so + 16, aSrc + k0 + 8, 16);
        cpa16(db + so,      bSrc + k0,     szb);
        cpa16(db + so + 16, bSrc + k0 + 8, szb);
    };

    const int niter = K / 32;
    issue(0, 0);
    cpcommit();
    int st = 0;
    for (int it = 0; it < niter; ++it) {
        if (it + 1 < niter) {
            issue(st ^ 1, (it + 1) * 32);
            cpcommit();
            cpwait<1>();
        } else {
            cpwait<0>();
        }
        __syncthreads();
        const fp16* base = sm + st * 2 * FMATB;
#pragma unroll
        for (int ks = 0; ks < 32; ks += 16) {
            uint32_t ah[4][4], bh[2][4];
#pragma unroll
            for (int mi = 0; mi < 4; mi++)
                ldsm4(ah[mi], su(base + (wm * 64 + mi * 16 + lrow) * SST + ks + lcol));
#pragma unroll
            for (int p = 0; p < 2; p++)
                ldsm4(bh[p], su(base + FMATB + (wn * 32 + p * 16 + lrow) * SST + ks + lcol));
#pragma unroll
            for (int mi = 0; mi < 4; mi++)
#pragma unroll
                for (int ni = 0; ni < 4; ni++) {
                    const int p = ni >> 1, q = ni & 1;
                    mmah(acc[mi][ni], ah[mi], bh[p][q], bh[p][q + 2]);
                }
        }
        __syncthreads();
        st ^= 1;
    }

#pragma unroll
    for (int mi = 0; mi < 4; mi++)
#pragma unroll
        for (int ni = 0; ni < 4; ni++) {
            int gn0 = bn + wn * 32 + ni * 8 + tg * 2;
#pragma unroll
            for (int half = 0; half < 2; half++) {
                int gm = bm + wm * 64 + mi * 16 + g + half * 8;
                if (gm >= Meff) continue;
                int orow = useRmap ? g_rmap[gm] : gm;
#pragma unroll
                for (int q = 0; q < 2; q++) {
                    int gn = gn0 + q;
                    if (gn >= N) continue;
                    float v = acc[mi][ni][half * 2 + q];
                    if (bias) v += bias[gn];
                    C[(size_t)orow * ldc + gn] = v;
                }
            }
        }
}

// -------------------- fp32 -> fp16 converter (+ build_map in last block) --------------
struct Seg { const float4* src; uint2* dst; int srcld4; int lc4; long long start; };
struct SegArr { Seg s[10]; long long total; };

__global__ void conv_all(SegArr sa, const int* __restrict__ lengths) {
    if (blockIdx.x == gridDim.x - 1) {
        __shared__ int cnt[20], off[21];
        int tid = threadIdx.x;
        if (tid < 20) {
            int c = 0;
            for (int b = 0; b < BQ; b++) c += (lengths[b] > tid);
            cnt[tid] = c;
        }
        __syncthreads();
        if (tid == 0) {
            off[0] = 0;
            for (int t = 0; t < 20; t++) off[t + 1] = off[t] + cnt[t];
            g_mact = off[20];
        }
        __syncthreads();
        for (int t = 0; t < 20; t++)
            for (int b = tid; b < cnt[t]; b += 256)
                g_rmap[off[t] + b] = b * TT + t;
        return;
    }
    long long i = (long long)blockIdx.x * blockDim.x + threadIdx.x;
    if (i >= sa.total) return;
    int k = 0;
#pragma unroll
    for (int j = 1; j < 10; j++) if (i >= sa.s[j].start) k = j;
    Seg sg = sa.s[k];
    long long idx = i - sg.start;
    int row = (int)(idx >> sg.lc4);
    int c   = (int)(idx & ((1 << sg.lc4) - 1));
    float4 v = sg.src[(long long)row * sg.srcld4 + c];
    __half2 a = __floats2half2_rn(v.x, v.y);
    __half2 b = __floats2half2_rn(v.z, v.w);
    uint2 o;
    o.x = *reinterpret_cast<uint32_t*>(&a);
    o.y = *reinterpret_cast<uint32_t*>(&b);
    sg.dst[idx] = o;
}

// -------------------- embedding gather (compact, fp16) --------------------
__global__ void gather_emb(const int* __restrict__ cap, const float* __restrict__ emb) {
    int i = blockIdx.x * blockDim.x + threadIdx.x;
    if (i >= BQ * TT * (EE / 4)) return;
    int r = i >> 6, e4 = i & 63;
    if (r >= g_mact) return;
    int tok = cap[g_rmap[r]];
    float4 v = reinterpret_cast<const float4*>(emb)[(size_t)tok * 64 + e4];
    __half2 a = __floats2half2_rn(v.x, v.y);
    __half2 b = __floats2half2_rn(v.z, v.w);
    uint2 o;
    o.x = *reinterpret_cast<uint32_t*>(&a);
    o.y = *reinterpret_cast<uint32_t*>(&b);
    reinterpret_cast<uint2*>(g_embf)[(size_t)r * 64 + e4] = o;
}

// -------------------- fused pre-pass: vproj + gates_x + init + zfill --------------------
__global__ void __launch_bounds__(256, 2) multi_pre(
    const int* __restrict__ lengths, float* __restrict__ out)
{
    extern __shared__ __align__(16) char smraw[];
    const int bx = blockIdx.x;
    if (bx < 98) {
        int y = bx % 49, kz = bx / 49;
        gemm_body(g_spf + kz * 256, DD, g_wvf + kz * 256, DD,
                  g_vpart[kz], KK_, BQ * KK_, KK_, 256, y * 128, 0,
                  nullptr, 0, smraw);
    } else if (bx < 418) {
        int i = bx - 98;
        int x = i & 15, y = i >> 4;
        int mact = g_mact;
        if (y * 128 >= mact) return;
        gemm_body(g_embf, EE, g_wihef, EE, g_gatesx, G4,
                  mact, G4, EE, y * 128, x * 128, nullptr, 0, smraw);
    } else if (bx < 514) {
        int i = bx - 418;
        int x = i % 24, kz = i / 24;
        gemm_body(g_glf + kz * 128, DD, g_wcatf + kz * 128, DD,
                  g_ipart[kz], 3072, BQ, 3072, 128, 0, x * 128,
                  nullptr, 0, smraw);
    } else {
        int i = bx - 514;
        float4 z = make_float4(0.f, 0.f, 0.f, 0.f);
#pragma unroll
        for (int k = 0; k < 4; k++) {
            int row = i * 4 + k;
            int b = row / TT, t = row % TT;
            if (lengths[b] > t) continue;
            float4* o = reinterpret_cast<float4*>(out + (size_t)row * VV);
            for (int q = threadIdx.x; q < VV / 4; q += 256) o[q] = z;
        }
    }
}

// -------------------- context kernel: s = alpha @ spatial + h_hist --------------------
__global__ void __launch_bounds__(256, 4) ctx_kernel()
{
    int r = blockIdx.x;
    if (r >= g_mact) return;
    __shared__ float sal[52];
    int tid = threadIdx.x;
    if (tid < KK_) sal[tid] = g_alpha[(size_t)r * 52 + tid];
    __syncthreads();
    int b = g_rmap[r] / TT;
    const __half2* sp2 = (const __half2*)(g_spf + (size_t)b * KK_ * DD);
    float ccx = 0.f, ccy = 0.f;
#pragma unroll
    for (int k = 0; k < KK_; k++) {
        float al = sal[k];
        float2 f = __half22float2(sp2[k * 256 + tid]);
        ccx = fmaf(al, f.x, ccx);
        ccy = fmaf(al, f.y, ccy);
    }
    float2 h = __half22float2(((const __half2*)g_hh)[(size_t)r * 256 + tid]);
    ((__half2*)g_sf)[(size_t)r * 256 + tid] = __floats2half2_rn(ccx + h.x, ccy + h.y);
}

// -------------------- vocab GEMM --------------------
__global__ void __launch_bounds__(256, 2) gemm_vocab(
    float* __restrict__ out, const float* __restrict__ bias)
{
    int mact = g_mact;
    if ((int)blockIdx.y * 128 >= mact) return;
    extern __shared__ __align__(16) char smraw[];
    gemm_body(g_sf, DD, g_wpf, DD, out, VV, mact, VV, DD,
              blockIdx.y * 128, blockIdx.x * 128, bias, 1, smraw);
}

// -------------------- pod-decomposed recurrence (flag sync) --------------------
#define RST2 520
#define RSM2 ((128 + 16) * RST2 * 2 + 49 * 52 * 4 + (3 * 52 + 49 + 45) * 4 + 128)

__global__ __launch_bounds__(256, 1) void recur_kernel(
    const float* __restrict__ b_hh,
    const int*   __restrict__ lengths,
    const float* __restrict__ bg,
    const float* __restrict__ wh,
    const float* __restrict__ bh_att,
    const float* __restrict__ b_init_h,
    const float* __restrict__ b_init_m,
    const float* __restrict__ b_ih,
    const float* __restrict__ bv)
{
    extern __shared__ __align__(16) char dsm[];
    fp16* sB = (fp16*)dsm;                   // [128][RST2] W slice (persistent)
    fp16* sA = sB + 128 * RST2;              // [16][RST2]  pod h rows
    float* sVP      = (float*)(sA + 16 * RST2);   // [49][52] vproj (j<16)
    float* sh_gh    = sVP + 49 * 52;
    float* sh_z     = sh_gh + 52;
    float* sh_alpha = sh_z + 52;
    float* sWH      = sh_alpha + 52;              // [49] wh
    int*   rs_cnt   = (int*)(sWH + 49);           // [21]
    int*   rs_off   = rs_cnt + 21;                // [22]
    unsigned* sh_rb = (unsigned*)(rs_off + 22);   // [2] flag bases

    const int c = blockIdx.x;
    const int p = c / 17, j = c % 17;
    const int pb0 = p * 16;
    const int b = pb0 + j;                   // phase2 batch (j<16 only)
    const int tid = threadIdx.x;
    const int w = tid >> 5, lane = tid & 31;
    const int g = lane >> 2, tg = lane & 3;
    const int lrow = lane & 15, lcol = (lane >> 4) * 8;
    const int wid = w;
    const float bh0 = bh_att[0];

    // ---- flag bases (read OWN flags: race-free, identical across pod CTAs) ----
    if (tid == 0) {
        sh_rb[0] = ldacq(&g_f1[p][j][0]);
        sh_rb[1] = ldacq(&g_f2[p][j][0]);
    }

    // ---- rs arrays + wh cache ----
    if (tid < 21) {
        int cc = 0;
        for (int bb = 0; bb < BQ; bb++) cc += (lengths[bb] > tid);
        rs_cnt[tid] = cc;
    }
    if (tid >= 32 && tid < 32 + KK_) sWH[tid - 32] = wh[tid - 32];
    __syncthreads();
    if (tid == 0) {
        rs_off[0] = 0;
        for (int u = 0; u < 21; u++) rs_off[u + 1] = rs_off[u] + rs_cnt[u];
    }
    __syncthreads();
    const unsigned rb1 = sh_rb[0], rb2 = sh_rb[1];

    int pod_len = 0;
#pragma unroll
    for (int q = 0; q < 16; q++) {
        int l = lengths[pb0 + q];
        pod_len = l > pod_len ? l : pod_len;
    }

    float hp[2], mr[2], gb[8];
    int len = 0;

    // ---- prologue: per-batch init reduce + vproj->smem (j<16) ----
    if (j < 16) {
        len = lengths[b];
#pragma unroll
        for (int blk = 0; blk < 6; blk++) {
            int base = blk * 512 + 2 * tid;
            float2 v = make_float2(0.f, 0.f);
#pragma unroll
            for (int q = 0; q < 4; q++) {
                float2 ip = *(const float2*)&g_ipart[q][b * 3072 + base];
                v.x += ip.x; v.y += ip.y;
            }
            if (blk == 0) {
                float2 bi = *(const float2*)&b_init_h[base];
                hp[0] = v.x + bi.x; hp[1] = v.y + bi.y;
                ((__half2*)g_hf)[b * 256 + tid] = __floats2half2_rn(hp[0], hp[1]);
            } else if (blk == 1) {
                float2 bi = *(const float2*)&b_init_m[base - 512];
                mr[0] = v.x + bi.x; mr[1] = v.y + bi.y;
            } else {
                int col = base - 1024;
                float2 bih = *(const float2*)&b_ih[col];
                float2 bhh = *(const float2*)&b_hh[col];
                gb[(blk - 2) * 2 + 0] = v.x + bih.x + bhh.x;
                gb[(blk - 2) * 2 + 1] = v.y + bih.y + bhh.y;
            }
        }
        for (int i = tid; i < KK_ * KK_; i += 256) {
            int kk = i / KK_, q = i % KK_;
            sVP[kk * 52 + q] =
                g_vpart[0][(size_t)(b * KK_ + kk) * KK_ + q] +
                g_vpart[1][(size_t)(b * KK_ + kk) * KK_ + q] + bv[q];
        }
    }
    // ---- preload W slice: rows [128j, 128j+128), K=512 ----
#pragma unroll
    for (int k = 0; k < 32; k++) {
        int cid = tid + k * 256;
        int row = cid >> 6, ch = cid & 63;
        *(float4*)(sB + row * RST2 + ch * 8) =
            *(const float4*)(g_wc2f + (size_t)(j * 128 + row) * DD + ch * 8);
    }
    __syncthreads();
    if (tid == 0) strel(&g_f2[p][j][0], rb2 + 1);   // h0 ready (dummy for j==16)

    for (int t = 0; t <= pod_len; t++) {
        // ---- wait: h(t-1) of all 16 batches ready ----
        if (tid < 16) waitflag(&g_f2[p][tid][0], rb2 + 1 + t);
        __syncthreads();
        // ---------------- phase 1: gates rows = h_pod @ Wslice^T ----------------
        {
#pragma unroll
            for (int k = 0; k < 4; k++) {
                int cid = tid + k * 256;
                int row = cid >> 6, ch = cid & 63;
                *(float4*)(sA + row * RST2 + ch * 8) =
                    *(const float4*)(g_hf + (size_t)(pb0 + row) * DD + ch * 8);
            }
            __syncthreads();

            float a0[2][4], a1[2][4];
#pragma unroll
            for (int q = 0; q < 2; q++)
#pragma unroll
                for (int i = 0; i < 4; i++) { a0[q][i] = 0.f; a1[q][i] = 0.f; }

#pragma unroll
            for (int ks = 0; ks < 256; ks += 16) {
                uint32_t x4[4], y4[4];
                ldsm4(x4, su(sA + lrow * RST2 + ks + lcol));
                ldsm4(y4, su(sB + (w * 16 + lrow) * RST2 + ks + lcol));
                mmah(a0[0], x4, y4[0], y4[2]);
                mmah(a0[1], x4, y4[1], y4[3]);
                ldsm4(x4, su(sA + lrow * RST2 + ks + 256 + lcol));
                ldsm4(y4, su(sB + (w * 16 + lrow) * RST2 + ks + 256 + lcol));
                mmah(a1[0], x4, y4[0], y4[2]);
                mmah(a1[1], x4, y4[1], y4[3]);
            }

#pragma unroll
            for (int q = 0; q < 2; q++) {
                int col = j * 128 + w * 16 + q * 8 + tg * 2;
                float* r0 = g_g2 + (size_t)(pb0 + g) * NW + col;
                float* r1 = g_g2 + (size_t)(pb0 + g + 8) * NW + col;
                r0[0] = a0[q][0] + a1[q][0]; r0[1] = a0[q][1] + a1[q][1];
                r1[0] = a0[q][2] + a1[q][2]; r1[1] = a0[q][3] + a1[q][3];
            }
        }
        __syncthreads();
        if (tid == 0) strel(&g_f1[p][j][0], rb1 + 1 + t);   // slice j done
        // ---------------- phase 2 (j < 16) ----------------
        const bool doattn = (j < 16) && (t >= 1) && (len > t - 1);
        const bool dolstm = (j < 16) && (t < TT) && (len > t);
        if (doattn || dolstm) {
            // prefetch gatesx (barrier-independent)
            float2 vi, vf, vg, vo;
            const float2* gx2 = dolstm
                ? (const float2*)(g_gatesx + (size_t)(rs_off[t] + b) * G4) : nullptr;
            if (dolstm) {
                vi = gx2[0 * 256 + tid]; vf = gx2[1 * 256 + tid];
                vg = gx2[2 * 256 + tid]; vo = gx2[3 * 256 + tid];
            }
            // wait: all 17 gate slices of step t
            if (tid < 17) waitflag(&g_f1[p][tid][0], rb1 + 1 + t);
            __syncthreads();
            const float* grow = g_g2 + (size_t)b * NW;
            if (doattn) {
                if (tid < KK_) sh_gh[tid] = bg[tid] + grow[2048 + tid];
                __syncthreads();
                for (int k = wid; k < KK_; k += 8) {
                    const float* vp = sVP + k * 52;
                    float s = 0.f;
                    for (int q = lane; q < KK_; q += 32) s += ftanh(vp[q] + sh_gh[q]) * sWH[q];
#pragma unroll
                    for (int o = 16; o; o >>= 1) s += __shfl_xor_sync(0xffffffffu, s, o);
                    if (lane == 0) sh_z[k] = s + bh0;
                }
                __syncthreads();
                if (wid == 0) {
                    float mx = -3.0e38f;
                    for (int k = lane; k < KK_; k += 32) mx = fmaxf(mx, sh_z[k]);
#pragma unroll
                    for (int o = 16; o; o >>= 1) mx = fmaxf(mx, __shfl_xor_sync(0xffffffffu, mx, o));
                    float sm = 0.f;
                    for (int k = lane; k < KK_; k += 32) { float e = __expf(sh_z[k] - mx); sh_alpha[k] = e; sm += e; }
#pragma unroll
                    for (int o = 16; o; o >>= 1) sm += __shfl_xor_sync(0xffffffffu, sm, o);
                    float inv = 1.f / sm;
                    for (int k = lane; k < KK_; k += 32) sh_alpha[k] *= inv;
                }
                __syncthreads();
                if (tid < KK_)
                    g_alpha[(size_t)(rs_off[t - 1] + b) * 52 + tid] = sh_alpha[tid];
            }
            if (dolstm) {
                const float2* gr2 = (const float2*)grow;
                float2 ri = gr2[0 * 256 + tid];
                float2 rf = gr2[1 * 256 + tid];
                float2 rg = gr2[2 * 256 + tid];
                float2 ro = gr2[3 * 256 + tid];
                float gix = vi.x + ri.x + gb[0], giy = vi.y + ri.y + gb[1];
                float gfx = vf.x + rf.x + gb[2], gfy = vf.y + rf.y + gb[3];
                float ggx = vg.x + rg.x + gb[4], ggy = vg.y + rg.y + gb[5];
                float gox = vo.x + ro.x + gb[6], goy = vo.y + ro.y + gb[7];
                float mnx = fsig(gfx) * mr[0] + fsig(gix) * ftanh(ggx);
                float mny = fsig(gfy) * mr[1] + fsig(giy) * ftanh(ggy);
                float hvx = fsig(gox) * ftanh(mnx);
                float hvy = fsig(goy) * ftanh(mny);
                mr[0] = mnx; mr[1] = mny;
                hp[0] = hvx; hp[1] = hvy;
                __half2 hh2 = __floats2half2_rn(hvx, hvy);
                ((__half2*)g_hf)[b * 256 + tid] = hh2;
                ((__half2*)g_hh)[(size_t)(rs_off[t] + b) * 256 + tid] = hh2;
            }
        }
        __syncthreads();
        if (tid == 0) strel(&g_f2[p][j][0], rb2 + 2 + t);   // batch j done, h(t) ready
    }
}

// -------------------- launch --------------------
extern "C" void kernel_launch(void* const* d_in, const int* in_sizes, int n_in,
                              void* d_out, int out_size)
{
    const float* spatial      = (const float*)d_in[0];
    const float* global_feats = (const float*)d_in[1];
    const int*   captions     = (const int*)d_in[2];
    const int*   lengths      = (const int*)d_in[3];
    const float* emb          = (const float*)d_in[4];
    const float* W_init_h     = (const float*)d_in[5];
    const float* b_init_h     = (const float*)d_in[6];
    const float* W_init_m     = (const float*)d_in[7];
    const float* b_init_m     = (const float*)d_in[8];
    const float* W_ih         = (const float*)d_in[9];
    const float* b_ih         = (const float*)d_in[10];
    const float* W_hh         = (const float*)d_in[11];
    const float* b_hh         = (const float*)d_in[12];
    const float* Wv           = (const float*)d_in[13];
    const float* bv           = (const float*)d_in[14];
    const float* Wg           = (const float*)d_in[15];
    const float* bg           = (const float*)d_in[16];
    const float* wh           = (const float*)d_in[17];
    const float* bh_att       = (const float*)d_in[18];
    const float* Wp           = (const float*)d_in[19];
    const float* bp           = (const float*)d_in[20];
    float* out = (float*)d_out;

#define GETP(var, sym) void* var; cudaGetSymbolAddress(&var, sym)
    GETP(p_glf, g_glf);      GETP(p_wihef, g_wihef);
    GETP(p_wcatf, g_wcatf);  GETP(p_wc2f, g_wc2f);
    GETP(p_wvf, g_wvf);      GETP(p_wpf, g_wpf);
    GETP(p_spf, g_spf);
#undef GETP

    const int FSM = 2 * 2 * FMATB * 2;                       // 40960 B
    cudaFuncSetAttribute(multi_pre, cudaFuncAttributeMaxDynamicSharedMemorySize, FSM);
    cudaFuncSetAttribute(gemm_vocab, cudaFuncAttributeMaxDynamicSharedMemorySize, FSM);
    cudaFuncSetAttribute(recur_kernel, cudaFuncAttributeMaxDynamicSharedMemorySize, RSM2);

    // ---- 1. convert fp32 -> fp16 (+ build active-row map) ----
    SegArr sa;
    long long pos = 0;
    auto seg = [&](int i, const float* src, void* dst, int srcld, int cols, int rows) {
        sa.s[i].src = (const float4*)src;
        sa.s[i].dst = (uint2*)dst;
        sa.s[i].srcld4 = srcld / 4;
        sa.s[i].lc4 = (cols / 4 == 64) ? 6 : 7;
        sa.s[i].start = pos;
        pos += (long long)rows * (cols / 4);
    };
    seg(0, global_feats, p_glf, DD, DD, BQ);
    seg(1, W_init_h, p_wcatf, DD, DD, DD);
    seg(2, W_init_m, (fp16*)p_wcatf + 512 * DD, DD, DD, DD);
    seg(3, W_ih, p_wihef, EE + DD, EE, G4);
    seg(4, W_ih + EE, (fp16*)p_wcatf + 1024 * DD, EE + DD, DD, G4);
    seg(5, W_hh, p_wc2f, DD, DD, G4);
    seg(6, Wg, (fp16*)p_wc2f + 2048 * DD, DD, DD, KK_);
    seg(7, Wv, p_wvf, DD, DD, KK_);
    seg(8, Wp, p_wpf, DD, DD, VV);
    seg(9, spatial, p_spf, DD, DD, BQ * KK_);
    sa.total = pos;
    conv_all<<<(unsigned)((pos + 255) / 256) + 1, 256>>>(sa, lengths);

    // ---- 2. gather caption embeddings (compact, fp16) ----
    gather_emb<<<(BQ * TT * (EE / 4) + 255) / 256, 256>>>(captions, emb);

    // ---- 3. fused pre-pass: vproj + gates_x + init + zfill ----
    multi_pre<<<1154, 256, FSM>>>(lengths, out);

    // ---- 4. recurrence (flag-synced pods) ----
    recur_kernel<<<136, 256, RSM2>>>(b_hh, lengths, bg, wh, bh_att,
                                     b_init_h, b_init_m, b_ih, bv);

    // ---- 5. context: s = alpha @ spatial + h_hist ----
    ctx_kernel<<<BQ * TT, 256>>>();

    // ---- 6. logits = s_compact @ Wp^T + bp, scattered via rmap ----
    gemm_vocab<<<dim3(79, 20), 256, FSM>>>(out, bp);
}